// round 1
// baseline (speedup 1.0000x reference)
#include <cuda_runtime.h>
#include <math.h>

#define NB 64
#define NP 196
#define NE 2048
#define ND 512
#define NA 512
#define NEMB 512
#define NV 10000
#define NL 52
#define NT 51
#define NX 2560   // EMB + ENC

// ---- output layout (flattened tuple, float32) ----
#define OUT_PRED   0
#define OUT_CAPS   32640000      // NB*NT*NV
#define OUT_DECLEN 32643328      // + NB*NL
#define OUT_ALPHA  32643392      // + NB
#define OUT_ORDER  33283136      // + NB*NT*NP

// ---- scratch (device globals; no allocation) ----
__device__ int   g_order[NB];
__device__ int   g_declen[NB];
__device__ float g_att1[(size_t)NB * NP * NA];   // 25.7 MB, sorted order
__device__ float g_h[2][NB * ND];
__device__ float g_c[NB * ND];
__device__ float g_alpha[NB * NP];
__device__ float g_x[NB * NX];
__device__ float g_mean[NB * NE];
__device__ float g_att2[NB * NA];
__device__ float g_gate[NB * NE];
__device__ float g_gates[NB * 4 * ND];

__device__ __forceinline__ float sigf(float x) { return 1.f / (1.f + expf(-x)); }

// ---------------------------------------------------------------
// init: stable descending argsort by length (O(B^2), B=64), plus
// caps/dec_len/order outputs
// ---------------------------------------------------------------
__global__ void k_sort(const int* __restrict__ clen, const int* __restrict__ caps,
                       float* __restrict__ out) {
    int i = threadIdx.x;
    __shared__ int len[NB];
    if (i < NB) len[i] = clen[i];
    __syncthreads();
    if (i < NB) {
        int li = len[i], r = 0;
        for (int j = 0; j < NB; j++) {
            int lj = len[j];
            if (lj > li || (lj == li && j < i)) r++;
        }
        g_order[r] = i;
    }
    __syncthreads();
    if (i < NB) {
        int src = g_order[i];
        int dl = len[src] - 1;
        g_declen[i] = dl;
        out[OUT_DECLEN + i] = (float)dl;
        out[OUT_ORDER + i] = (float)src;
        for (int t = 0; t < NL; t++)
            out[OUT_CAPS + i * NL + t] = (float)caps[src * NL + t];
    }
}

// mean over pixels (per sorted batch row)
__global__ void k_mean(const float* __restrict__ enc) {
    int b = blockIdx.x, tid = threadIdx.x;
    const float* base = enc + (size_t)g_order[b] * NP * NE;
    for (int e = tid; e < NE; e += 256) {
        float s = 0.f;
        for (int p = 0; p < NP; p++) s += base[(size_t)p * NE + e];
        g_mean[b * NE + e] = s * (1.0f / NP);
    }
}

// h0/c0 = mean_enc @ initW + b
__global__ void k_inithc(const float* __restrict__ HW, const float* __restrict__ Hb,
                         const float* __restrict__ CW, const float* __restrict__ Cb) {
    int b = blockIdx.x, tid = threadIdx.x;
    __shared__ float m[NE];
    for (int e = tid; e < NE; e += 256) m[e] = g_mean[b * NE + e];
    __syncthreads();
    for (int d = tid; d < ND; d += 256) {
        float sh = 0.f, sc = 0.f;
        for (int e = 0; e < NE; e++) {
            float me = m[e];
            sh += me * HW[(size_t)e * ND + d];
            sc += me * CW[(size_t)e * ND + d];
        }
        g_h[0][b * ND + d] = sh + Hb[d];
        g_c[b * ND + d] = sc + Cb[d];
    }
}

// ---------------------------------------------------------------
// att1 = enc_sorted @ att_enc_W + b : (12544 x 512), K=2048
// tile 64m x 64n, Ktile 32. grid (bn=8, bm=196) so the 8 n-tiles of one
// m-tile run back-to-back (A tile stays hot in L2).
// ---------------------------------------------------------------
__global__ void k_att1(const float* __restrict__ enc, const float* __restrict__ W,
                       const float* __restrict__ bias) {
    __shared__ float As[32][68];
    __shared__ float Bs[32][68];
    __shared__ int rowBase[64];
    const int bn = blockIdx.x, bm = blockIdx.y;
    const int tid = threadIdx.x;
    const int row0 = bm * 64;
    if (tid < 64) {
        int m = row0 + tid;
        rowBase[tid] = g_order[m / NP] * NP + (m % NP);
    }
    __syncthreads();
    const int tx = tid & 15, ty = tid >> 4;
    float acc[4][4] = {};
    for (int k0 = 0; k0 < NE; k0 += 32) {
#pragma unroll
        for (int i = 0; i < 8; i++) {
            int l = i * 256 + tid;
            int m = l >> 5, k = l & 31;
            As[k][m] = enc[(size_t)rowBase[m] * NE + k0 + k];
        }
#pragma unroll
        for (int i = 0; i < 8; i++) {
            int l = i * 256 + tid;
            int k = l >> 6, n = l & 63;
            Bs[k][n] = W[(size_t)(k0 + k) * NA + bn * 64 + n];
        }
        __syncthreads();
#pragma unroll
        for (int kk = 0; kk < 32; kk++) {
            float4 a4 = *(const float4*)&As[kk][ty * 4];
            float4 b4 = *(const float4*)&Bs[kk][tx * 4];
            acc[0][0] += a4.x * b4.x; acc[0][1] += a4.x * b4.y; acc[0][2] += a4.x * b4.z; acc[0][3] += a4.x * b4.w;
            acc[1][0] += a4.y * b4.x; acc[1][1] += a4.y * b4.y; acc[1][2] += a4.y * b4.z; acc[1][3] += a4.y * b4.w;
            acc[2][0] += a4.z * b4.x; acc[2][1] += a4.z * b4.y; acc[2][2] += a4.z * b4.z; acc[2][3] += a4.z * b4.w;
            acc[3][0] += a4.w * b4.x; acc[3][1] += a4.w * b4.y; acc[3][2] += a4.w * b4.z; acc[3][3] += a4.w * b4.w;
        }
        __syncthreads();
    }
#pragma unroll
    for (int i = 0; i < 4; i++) {
        size_t m = row0 + ty * 4 + i;
#pragma unroll
        for (int j = 0; j < 4; j++)
            g_att1[m * NA + bn * 64 + tx * 4 + j] = acc[i][j] + bias[bn * 64 + tx * 4 + j];
    }
}

// ---------------------------------------------------------------
// per step: att2 = h @ att_dec_W + b, gatep = sigmoid(h @ fbeta_W + b)
// one GEMM over j in [0,2560): full batch per block (weight reuse).
// tile 64b x 16j, K=512.
// ---------------------------------------------------------------
__global__ void k_hproj(int ph, const float* __restrict__ attW, const float* __restrict__ attb,
                        const float* __restrict__ fbW, const float* __restrict__ fbb) {
    const int j0 = blockIdx.x * 16;
    const int tid = threadIdx.x;
    const float* h_in = g_h[ph];
    __shared__ float Xs[32][68];
    __shared__ float Ws[32][16];
    const int tx = tid & 15, ty = tid >> 4;
    float acc[4] = {0.f, 0.f, 0.f, 0.f};
    const bool isAtt = (j0 < NA);
    const float* W = isAtt ? attW : fbW;
    const int Jw = isAtt ? NA : NE;
    const int jj0 = isAtt ? j0 : (j0 - NA);
    for (int k0 = 0; k0 < ND; k0 += 32) {
#pragma unroll
        for (int i = 0; i < 8; i++) {
            int l = i * 256 + tid;
            int bb = l >> 5, k = l & 31;
            Xs[k][bb] = h_in[bb * ND + k0 + k];
        }
#pragma unroll
        for (int i = 0; i < 2; i++) {
            int ll = i * 256 + tid;
            int k = ll >> 4, j = ll & 15;
            Ws[k][j] = W[(size_t)(k0 + k) * Jw + jj0 + j];
        }
        __syncthreads();
#pragma unroll
        for (int kk = 0; kk < 32; kk++) {
            float4 a4 = *(const float4*)&Xs[kk][ty * 4];
            float w = Ws[kk][tx];
            acc[0] += a4.x * w; acc[1] += a4.y * w; acc[2] += a4.z * w; acc[3] += a4.w * w;
        }
        __syncthreads();
    }
#pragma unroll
    for (int i = 0; i < 4; i++) {
        int b = ty * 4 + i;
        if (isAtt) {
            g_att2[b * NA + j0 + tx] = acc[i] + attb[j0 + tx];
        } else {
            int e = jj0 + tx;
            g_gate[b * NE + e] = sigf(acc[i] + fbb[e]);
        }
    }
}

// ---------------------------------------------------------------
// per step: e = relu(att1 + att2) @ w + b0, softmax over pixels -> alpha;
// also write embedding slice of x. One block per batch row.
// ---------------------------------------------------------------
__global__ void k_alpha(int t, const float* __restrict__ fullw, const float* __restrict__ fullb,
                        const float* __restrict__ embW, const int* __restrict__ caps,
                        float* __restrict__ out) {
    const int b = blockIdx.x, tid = threadIdx.x;
    const int warp = tid >> 5, lane = tid & 31;
    float* aout = out + OUT_ALPHA + ((size_t)b * NT + t) * NP;
    if (t >= g_declen[b]) {
        for (int p = tid; p < NP; p += 256) aout[p] = 0.f;
        return;
    }
    __shared__ float att2s[NA];
    __shared__ float ws[NA];
    __shared__ float ev[NP];
    __shared__ float red[8];
    __shared__ float smax, ssum;
    for (int i = tid; i < NA; i += 256) { att2s[i] = g_att2[b * NA + i]; ws[i] = fullw[i]; }
    {   // x[:512] = embedding row
        int cap = caps[g_order[b] * NL + t];
        for (int i = tid; i < NEMB; i += 256) g_x[b * NX + i] = embW[(size_t)cap * NEMB + i];
    }
    __syncthreads();
    const float fb = fullb[0];
    for (int p = warp; p < NP; p += 8) {
        const float* a1 = g_att1 + ((size_t)(b * NP + p)) * NA;
        float s = 0.f;
#pragma unroll 4
        for (int a = lane; a < NA; a += 32) {
            float v = a1[a] + att2s[a];
            s += fmaxf(v, 0.f) * ws[a];
        }
#pragma unroll
        for (int o = 16; o; o >>= 1) s += __shfl_xor_sync(0xffffffffu, s, o);
        if (lane == 0) ev[p] = s + fb;
    }
    __syncthreads();
    float v = (tid < NP) ? ev[tid] : -3.0e38f;
    float m = v;
#pragma unroll
    for (int o = 16; o; o >>= 1) m = fmaxf(m, __shfl_xor_sync(0xffffffffu, m, o));
    if (lane == 0) red[warp] = m;
    __syncthreads();
    if (tid == 0) { float mm = red[0]; for (int i = 1; i < 8; i++) mm = fmaxf(mm, red[i]); smax = mm; }
    __syncthreads();
    float ex = (tid < NP) ? expf(v - smax) : 0.f;
    float s2 = ex;
#pragma unroll
    for (int o = 16; o; o >>= 1) s2 += __shfl_xor_sync(0xffffffffu, s2, o);
    if (lane == 0) red[warp] = s2;
    __syncthreads();
    if (tid == 0) { float ss = 0.f; for (int i = 0; i < 8; i++) ss += red[i]; ssum = ss; }
    __syncthreads();
    if (tid < NP) {
        float a = ex / ssum;
        g_alpha[b * NP + tid] = a;
        aout[tid] = a;
    }
}

// ---------------------------------------------------------------
// per step: awe[e] = sum_p alpha_p * enc[b,p,e];  x[512+e] = gate*awe.
// grid (echunk=8, b=64). HBM-bound (103 MB/step).
// ---------------------------------------------------------------
__global__ void k_awex(int t, const float* __restrict__ enc) {
    const int b = blockIdx.y;
    if (t >= g_declen[b]) return;
    const int tid = threadIdx.x;
    const int e = blockIdx.x * 256 + tid;
    __shared__ float al[NP];
    for (int i = tid; i < NP; i += 256) al[i] = g_alpha[b * NP + i];
    __syncthreads();
    const float* eb = enc + ((size_t)g_order[b] * NP) * NE + e;
    float awe = 0.f;
#pragma unroll 4
    for (int p = 0; p < NP; p++) awe += al[p] * eb[(size_t)p * NE];
    g_x[b * NX + NEMB + e] = g_gate[b * NE + e] * awe;
}

// ---------------------------------------------------------------
// per step: gates = [x,h] @ [Wih;Whh]^T + biases. 64b x 16j tiles, K=3072.
// ---------------------------------------------------------------
__global__ void k_gates(int ph, const float* __restrict__ Wih, const float* __restrict__ Whh,
                        const float* __restrict__ bih, const float* __restrict__ bhh) {
    const int j0 = blockIdx.x * 16;
    const int tid = threadIdx.x;
    const float* h_in = g_h[ph];
    __shared__ float Xs[32][68];
    __shared__ float Ws[32][17];
    const int tx = tid & 15, ty = tid >> 4;
    float acc[4] = {0.f, 0.f, 0.f, 0.f};
    for (int c = 0; c < 96; c++) {
        int k0 = c * 32;
#pragma unroll
        for (int i = 0; i < 8; i++) {
            int l = i * 256 + tid;
            int bb = l >> 5, k = l & 31;
            int kg = k0 + k;
            Xs[k][bb] = (kg < NX) ? g_x[bb * NX + kg] : h_in[bb * ND + kg - NX];
        }
#pragma unroll
        for (int i = 0; i < 2; i++) {
            int ll = i * 256 + tid;
            int j = ll >> 5, k = ll & 31;
            int kg = k0 + k, jg = j0 + j;
            Ws[k][j] = (kg < NX) ? Wih[(size_t)jg * NX + kg] : Whh[(size_t)jg * ND + kg - NX];
        }
        __syncthreads();
#pragma unroll
        for (int kk = 0; kk < 32; kk++) {
            float4 a4 = *(const float4*)&Xs[kk][ty * 4];
            float w = Ws[kk][tx];
            acc[0] += a4.x * w; acc[1] += a4.y * w; acc[2] += a4.z * w; acc[3] += a4.w * w;
        }
        __syncthreads();
    }
    int j = j0 + tx;
    float bb2 = bih[j] + bhh[j];
#pragma unroll
    for (int i = 0; i < 4; i++) g_gates[(ty * 4 + i) * (4 * ND) + j] = acc[i] + bb2;
}

// LSTM pointwise update (active rows only; masked rows keep outputs zeroed downstream)
__global__ void k_lstmpw(int t, int ph) {
    const int b = blockIdx.x;
    if (t >= g_declen[b]) return;
    const int d = threadIdx.x;
    const float* g = g_gates + b * (4 * ND);
    float i_ = sigf(g[d]);
    float f_ = sigf(g[ND + d]);
    float gg = tanhf(g[2 * ND + d]);
    float o_ = sigf(g[3 * ND + d]);
    float c = f_ * g_c[b * ND + d] + i_ * gg;
    g_c[b * ND + d] = c;
    g_h[ph ^ 1][b * ND + d] = o_ * tanhf(c);
}

// ---------------------------------------------------------------
// per step: preds = h_new @ fc_W + fc_b (masked rows -> 0).
// tile 16b x 128v, K=512. grid (79, 4).
// ---------------------------------------------------------------
__global__ void k_fc(int t, int ph, const float* __restrict__ Wf, const float* __restrict__ bf,
                     float* __restrict__ out) {
    const int v0 = blockIdx.x * 128;
    const int b0 = blockIdx.y * 16;
    const int tid = threadIdx.x;
    const float* h_new = g_h[ph ^ 1];
    __shared__ float hs[16][ND];
    for (int i = tid; i < 16 * ND; i += 256)
        hs[i >> 9][i & 511] = h_new[(b0 + (i >> 9)) * ND + (i & 511)];
    __syncthreads();
    const int v = v0 + (tid & 127);
    const int bg = (tid >> 7) * 8;
    if (v >= NV) return;
    float acc[8] = {0.f, 0.f, 0.f, 0.f, 0.f, 0.f, 0.f, 0.f};
    const float* wc = Wf + v;
    for (int k = 0; k < ND; k += 4) {
        float w0 = wc[(size_t)k * NV];
        float w1 = wc[(size_t)(k + 1) * NV];
        float w2 = wc[(size_t)(k + 2) * NV];
        float w3 = wc[(size_t)(k + 3) * NV];
#pragma unroll
        for (int i = 0; i < 8; i++) {
            float4 h4 = *(const float4*)&hs[bg + i][k];
            acc[i] += h4.x * w0 + h4.y * w1 + h4.z * w2 + h4.w * w3;
        }
    }
    const float bias = bf[v];
#pragma unroll
    for (int i = 0; i < 8; i++) {
        int b = b0 + bg + i;
        float r = (t < g_declen[b]) ? (acc[i] + bias) : 0.f;
        out[(size_t)(b * NT + t) * NV + v] = r;
    }
}

// ---------------------------------------------------------------
extern "C" void kernel_launch(void* const* d_in, const int* in_sizes, int n_in,
                              void* d_out, int out_size) {
    (void)in_sizes; (void)n_in; (void)out_size;
    const float* enc     = (const float*)d_in[0];
    const int*   caps    = (const int*)d_in[1];
    const int*   clen    = (const int*)d_in[2];
    const float* embW    = (const float*)d_in[3];
    const float* attEncW = (const float*)d_in[4];
    const float* attEncB = (const float*)d_in[5];
    const float* attDecW = (const float*)d_in[6];
    const float* attDecB = (const float*)d_in[7];
    const float* fullW   = (const float*)d_in[8];
    const float* fullB   = (const float*)d_in[9];
    const float* Wih     = (const float*)d_in[10];
    const float* Whh     = (const float*)d_in[11];
    const float* bih     = (const float*)d_in[12];
    const float* bhh     = (const float*)d_in[13];
    const float* iHW     = (const float*)d_in[14];
    const float* iHb     = (const float*)d_in[15];
    const float* iCW     = (const float*)d_in[16];
    const float* iCb     = (const float*)d_in[17];
    const float* fbW     = (const float*)d_in[18];
    const float* fbb     = (const float*)d_in[19];
    const float* fcW     = (const float*)d_in[20];
    const float* fcb     = (const float*)d_in[21];
    float* out = (float*)d_out;

    k_sort<<<1, 64>>>(clen, caps, out);
    k_mean<<<NB, 256>>>(enc);
    k_inithc<<<NB, 256>>>(iHW, iHb, iCW, iCb);
    k_att1<<<dim3(8, 196), 256>>>(enc, attEncW, attEncB);

    for (int t = 0; t < NT; t++) {
        int ph = t & 1;
        k_hproj<<<NX / 16, 256>>>(ph, attDecW, attDecB, fbW, fbb);
        k_alpha<<<NB, 256>>>(t, fullW, fullB, embW, caps, out);
        k_awex<<<dim3(NE / 256, NB), 256>>>(t, enc);
        k_gates<<<(4 * ND) / 16, 256>>>(ph, Wih, Whh, bih, bhh);
        k_lstmpw<<<NB, ND>>>(t, ph);
        k_fc<<<dim3((NV + 127) / 128, 4), 256>>>(t, ph, fcW, fcb, out);
    }
}

// round 4
// speedup vs baseline: 1.3441x; 1.3441x over previous
#include <cuda_runtime.h>
#include <math.h>

#define NB 64
#define NP 196
#define NE 2048
#define ND 512
#define NA 512
#define NEMB 512
#define NV 10000
#define NL 52
#define NT 51
#define NX 2560   // EMB + ENC

// ---- output layout (flattened tuple, float32) ----
#define OUT_PRED   0
#define OUT_CAPS   32640000      // NB*NT*NV
#define OUT_DECLEN 32643328      // + NB*NL
#define OUT_ALPHA  32643392      // + NB
#define OUT_ORDER  33283136      // + NB*NT*NP

typedef unsigned long long ull;

// ---- scratch (device globals; no allocation) ----
__device__ int   g_order[NB];
__device__ int   g_declen[NB];
__device__ float g_att1[(size_t)NB * NP * NA];
__device__ float g_h[2][NB * ND];
__device__ float g_c[NB * ND];
__device__ float g_alpha[NB * NP];
__device__ float g_x[NB * NX];
__device__ float g_att2[NB * NA];
__device__ float g_gate[NB * NE];
__device__ float g_gates[NB * 4 * ND];

__device__ __forceinline__ float sigf(float x) { return 1.f / (1.f + expf(-x)); }

// ---- packed f32x2 FMA helpers ----
__device__ __forceinline__ ull pack2(float x, float y) {
    ull d; asm("mov.b64 %0, {%1, %2};" : "=l"(d) : "f"(x), "f"(y)); return d;
}
__device__ __forceinline__ void fma2(ull& d, ull a, ull b) {
    asm("fma.rn.f32x2 %0, %1, %2, %0;" : "+l"(d) : "l"(a), "l"(b));
}
__device__ __forceinline__ void unpack2(ull v, float& lo, float& hi) {
    asm("mov.b64 {%0, %1}, %2;" : "=f"(lo), "=f"(hi) : "l"(v));
}

// ---- cp.async helpers ----
__device__ __forceinline__ void cpa4(void* dst, const void* src) {
    unsigned sd = (unsigned)__cvta_generic_to_shared(dst);
    asm volatile("cp.async.ca.shared.global [%0], [%1], 4;" :: "r"(sd), "l"(src));
}
__device__ __forceinline__ void cpa16(void* dst, const void* src) {
    unsigned sd = (unsigned)__cvta_generic_to_shared(dst);
    asm volatile("cp.async.cg.shared.global [%0], [%1], 16;" :: "r"(sd), "l"(src));
}
#define CP_COMMIT asm volatile("cp.async.commit_group;")
#define CP_WAIT1  asm volatile("cp.async.wait_group 1;")
#define CP_WAIT0  asm volatile("cp.async.wait_group 0;")

// ---------------------------------------------------------------
__global__ void k_sort(const int* __restrict__ clen, const int* __restrict__ caps,
                       float* __restrict__ out) {
    int i = threadIdx.x;
    __shared__ int len[NB];
    if (i < NB) len[i] = clen[i];
    __syncthreads();
    if (i < NB) {
        int li = len[i], r = 0;
        for (int j = 0; j < NB; j++) {
            int lj = len[j];
            if (lj > li || (lj == li && j < i)) r++;
        }
        g_order[r] = i;
    }
    __syncthreads();
    if (i < NB) {
        int src = g_order[i];
        int dl = len[src] - 1;
        g_declen[i] = dl;
        out[OUT_DECLEN + i] = (float)dl;
        out[OUT_ORDER + i] = (float)src;
        for (int t = 0; t < NL; t++)
            out[OUT_CAPS + i * NL + t] = (float)caps[src * NL + t];
    }
}

// mean over pixels: grid (8 echunks, 64 b)
__device__ float g_mean[NB * NE];
__global__ void k_mean(const float* __restrict__ enc) {
    int b = blockIdx.y;
    int e = blockIdx.x * 256 + threadIdx.x;
    const float* base = enc + (size_t)g_order[b] * NP * NE + e;
    float s = 0.f;
#pragma unroll 7
    for (int p = 0; p < NP; p++) s += base[(size_t)p * NE];
    g_mean[b * NE + e] = s * (1.0f / NP);
}

__global__ void k_inithc(const float* __restrict__ HW, const float* __restrict__ Hb,
                         const float* __restrict__ CW, const float* __restrict__ Cb) {
    int b = blockIdx.x, tid = threadIdx.x;
    __shared__ float m[NE];
    for (int e = tid; e < NE; e += 256) m[e] = g_mean[b * NE + e];
    __syncthreads();
    for (int d = tid; d < ND; d += 256) {
        float sh = 0.f, sc = 0.f;
        for (int e = 0; e < NE; e++) {
            float me = m[e];
            sh += me * HW[(size_t)e * ND + d];
            sc += me * CW[(size_t)e * ND + d];
        }
        g_h[0][b * ND + d] = sh + Hb[d];
        g_c[b * ND + d] = sc + Cb[d];
    }
}

// ---------------------------------------------------------------
// att1 = enc_sorted @ att_enc_W + b. 64m x 64n tiles, K=2048, Kchunk=32,
// cp.async double-buffered, f32x2 inner (pairs over m).
// ---------------------------------------------------------------
__global__ void k_att1(const float* __restrict__ enc, const float* __restrict__ W,
                       const float* __restrict__ bias) {
    __shared__ float As[2][32][68];
    __shared__ float Bs[2][32][64];
    __shared__ int rowBase[64];
    const int bn = blockIdx.x, bm = blockIdx.y;
    const int tid = threadIdx.x;
    const int row0 = bm * 64;
    if (tid < 64) {
        int m = row0 + tid;
        rowBase[tid] = g_order[m / NP] * NP + (m % NP);
    }
    __syncthreads();
    const int tx = tid & 15, ty = tid >> 4;

#define ATT1_LOAD(k0, buf) do { \
    _Pragma("unroll") \
    for (int i = 0; i < 8; i++) { \
        int l = i * 256 + tid; int mm = l >> 5, kk2 = l & 31; \
        cpa4(&As[buf][kk2][mm], &enc[(size_t)rowBase[mm] * NE + (k0) + kk2]); \
    } \
    _Pragma("unroll") \
    for (int i = 0; i < 2; i++) { \
        int l = i * 256 + tid; int kk2 = l >> 4, n4 = (l & 15) * 4; \
        cpa16(&Bs[buf][kk2][n4], &W[(size_t)((k0) + kk2) * NA + bn * 64 + n4]); \
    } \
    CP_COMMIT; } while (0)

    ATT1_LOAD(0, 0);
    ull acc[2][4] = {};
    for (int c = 0; c < 64; c++) {
        int buf = c & 1;
        if (c + 1 < 64) { ATT1_LOAD((c + 1) * 32, buf ^ 1); CP_WAIT1; }
        else { CP_WAIT0; }
        __syncthreads();
#pragma unroll
        for (int kk = 0; kk < 32; kk++) {
            float4 a4 = *(const float4*)&As[buf][kk][ty * 4];
            float4 b4 = *(const float4*)&Bs[buf][kk][tx * 4];
            ull* ap = (ull*)&a4;
            ull w0 = pack2(b4.x, b4.x), w1 = pack2(b4.y, b4.y);
            ull w2 = pack2(b4.z, b4.z), w3 = pack2(b4.w, b4.w);
            fma2(acc[0][0], ap[0], w0); fma2(acc[0][1], ap[0], w1);
            fma2(acc[0][2], ap[0], w2); fma2(acc[0][3], ap[0], w3);
            fma2(acc[1][0], ap[1], w0); fma2(acc[1][1], ap[1], w1);
            fma2(acc[1][2], ap[1], w2); fma2(acc[1][3], ap[1], w3);
        }
        __syncthreads();
    }
#pragma unroll
    for (int p = 0; p < 2; p++) {
#pragma unroll
        for (int j = 0; j < 4; j++) {
            int col = bn * 64 + tx * 4 + j;
            float lo, hi;
            unpack2(acc[p][j], lo, hi);
            size_t m0 = row0 + ty * 4 + 2 * p;
            float bv = bias[col];
            g_att1[m0 * NA + col] = lo + bv;
            g_att1[(m0 + 1) * NA + col] = hi + bv;
        }
    }
#undef ATT1_LOAD
}

// ---------------------------------------------------------------
// hproj: att2 = h @ att_dec_W + b ; gate = sigmoid(h @ fbeta_W + b)
// W layout: [k][j] (j contiguous). 64b x 16j tiles, K=512, Kchunk=32,
// double-buffered, f32x2 (pairs over b). grid 160.
// ---------------------------------------------------------------
__global__ void k_hproj(int ph, const float* __restrict__ attW, const float* __restrict__ attb,
                        const float* __restrict__ fbW, const float* __restrict__ fbb) {
    __shared__ float Xs[2][32][68];
    __shared__ float Ws[2][32][17];
    const int j0 = blockIdx.x * 16;
    const int tid = threadIdx.x;
    const float* h_in = g_h[ph];
    const bool isAtt = (j0 < NA);
    const float* W = isAtt ? attW : fbW;
    const int Jw = isAtt ? NA : NE;
    const int jj0 = isAtt ? j0 : (j0 - NA);
    const int tx = tid & 15, ty = tid >> 4;

#define HP_LOAD(k0, buf) do { \
    _Pragma("unroll") \
    for (int i = 0; i < 8; i++) { \
        int l = i * 256 + tid; int bb = l >> 5, kk2 = l & 31; \
        cpa4(&Xs[buf][kk2][bb], &h_in[bb * ND + (k0) + kk2]); \
    } \
    _Pragma("unroll") \
    for (int i = 0; i < 2; i++) { \
        int l = i * 256 + tid; int kk2 = l >> 4, j = l & 15; \
        cpa4(&Ws[buf][kk2][j], &W[(size_t)((k0) + kk2) * Jw + jj0 + j]); \
    } \
    CP_COMMIT; } while (0)

    HP_LOAD(0, 0);
    ull acc[2] = {};
    for (int c = 0; c < 16; c++) {
        int buf = c & 1;
        if (c + 1 < 16) { HP_LOAD((c + 1) * 32, buf ^ 1); CP_WAIT1; }
        else { CP_WAIT0; }
        __syncthreads();
#pragma unroll
        for (int kk = 0; kk < 32; kk++) {
            float4 a4 = *(const float4*)&Xs[buf][kk][ty * 4];
            ull* ap = (ull*)&a4;
            float w = Ws[buf][kk][tx];
            ull w2 = pack2(w, w);
            fma2(acc[0], ap[0], w2);
            fma2(acc[1], ap[1], w2);
        }
        __syncthreads();
    }
#pragma unroll
    for (int p = 0; p < 2; p++) {
        float lo, hi;
        unpack2(acc[p], lo, hi);
        int b0r = ty * 4 + 2 * p;
        if (isAtt) {
            float bv = attb[j0 + tx];
            g_att2[b0r * NA + j0 + tx] = lo + bv;
            g_att2[(b0r + 1) * NA + j0 + tx] = hi + bv;
        } else {
            int e = jj0 + tx;
            float bv = fbb[e];
            g_gate[b0r * NE + e] = sigf(lo + bv);
            g_gate[(b0r + 1) * NE + e] = sigf(hi + bv);
        }
    }
#undef HP_LOAD
}

// ---------------------------------------------------------------
// alpha: e = relu(att1+att2)@w + b, softmax -> alpha; writes emb slice of x.
// ---------------------------------------------------------------
__global__ void k_alpha(int t, const float* __restrict__ fullw, const float* __restrict__ fullb,
                        const float* __restrict__ embW, const int* __restrict__ caps,
                        float* __restrict__ out) {
    const int b = blockIdx.x, tid = threadIdx.x;
    const int warp = tid >> 5, lane = tid & 31;
    float* aout = out + OUT_ALPHA + ((size_t)b * NT + t) * NP;
    if (t >= g_declen[b]) {
        for (int p = tid; p < NP; p += 256) aout[p] = 0.f;
        return;
    }
    __shared__ float att2s[NA];
    __shared__ float ws[NA];
    __shared__ float ev[NP];
    __shared__ float red[8];
    __shared__ float smax, ssum;
    for (int i = tid; i < NA; i += 256) { att2s[i] = g_att2[b * NA + i]; ws[i] = fullw[i]; }
    {
        int cap = caps[g_order[b] * NL + t];
        for (int i = tid; i < NEMB; i += 256) g_x[b * NX + i] = embW[(size_t)cap * NEMB + i];
    }
    __syncthreads();
    const float fb = fullb[0];
    for (int p = warp; p < NP; p += 8) {
        const float* a1 = g_att1 + ((size_t)(b * NP + p)) * NA;
        float s = 0.f;
#pragma unroll 4
        for (int a = lane; a < NA; a += 32) {
            float v = a1[a] + att2s[a];
            s += fmaxf(v, 0.f) * ws[a];
        }
#pragma unroll
        for (int o = 16; o; o >>= 1) s += __shfl_xor_sync(0xffffffffu, s, o);
        if (lane == 0) ev[p] = s + fb;
    }
    __syncthreads();
    float v = (tid < NP) ? ev[tid] : -3.0e38f;
    float m = v;
#pragma unroll
    for (int o = 16; o; o >>= 1) m = fmaxf(m, __shfl_xor_sync(0xffffffffu, m, o));
    if (lane == 0) red[warp] = m;
    __syncthreads();
    if (tid == 0) { float mm = red[0]; for (int i = 1; i < 8; i++) mm = fmaxf(mm, red[i]); smax = mm; }
    __syncthreads();
    float ex = (tid < NP) ? expf(v - smax) : 0.f;
    float s2 = ex;
#pragma unroll
    for (int o = 16; o; o >>= 1) s2 += __shfl_xor_sync(0xffffffffu, s2, o);
    if (lane == 0) red[warp] = s2;
    __syncthreads();
    if (tid == 0) { float ss = 0.f; for (int i = 0; i < 8; i++) ss += red[i]; ssum = ss; }
    __syncthreads();
    if (tid < NP) {
        float a = ex / ssum;
        g_alpha[b * NP + tid] = a;
        aout[tid] = a;
    }
}

// ---------------------------------------------------------------
// awex: awe[e] = sum_p alpha_p enc[b,p,e]; x[512+e] = gate*awe
// ---------------------------------------------------------------
__global__ void k_awex(int t, const float* __restrict__ enc) {
    const int b = blockIdx.y;
    if (t >= g_declen[b]) return;
    const int tid = threadIdx.x;
    const int e = blockIdx.x * 256 + tid;
    __shared__ float al[NP];
    for (int i = tid; i < NP; i += 256) al[i] = g_alpha[b * NP + i];
    __syncthreads();
    const float* eb = enc + ((size_t)g_order[b] * NP) * NE + e;
    float awe = 0.f;
#pragma unroll 7
    for (int p = 0; p < NP; p++) awe += al[p] * eb[(size_t)p * NE];
    g_x[b * NX + NEMB + e] = g_gate[b * NE + e] * awe;
}

// ---------------------------------------------------------------
// gates = [x,h] @ [Wih;Whh]^T + biases. W layout [j][k] (k contiguous).
// 64b x 16j tiles, K=3072, Kchunk 32, double-buffered, f32x2 b-pairs.
// ---------------------------------------------------------------
__global__ void k_gates(int ph, const float* __restrict__ Wih, const float* __restrict__ Whh,
                        const float* __restrict__ bih, const float* __restrict__ bhh) {
    __shared__ float Xs[2][32][68];
    __shared__ float Ws[2][32][17];
    const int j0 = blockIdx.x * 16;
    const int tid = threadIdx.x;
    const float* h_in = g_h[ph];
    const int tx = tid & 15, ty = tid >> 4;

#define GA_LOAD(k0, buf) do { \
    const float* xsrc; int xoff; \
    if ((k0) < NX) { xsrc = g_x; xoff = (k0); } else { xsrc = h_in; xoff = (k0) - NX; } \
    const int xstride = ((k0) < NX) ? NX : ND; \
    _Pragma("unroll") \
    for (int i = 0; i < 8; i++) { \
        int l = i * 256 + tid; int bb = l >> 5, kk2 = l & 31; \
        cpa4(&Xs[buf][kk2][bb], &xsrc[bb * xstride + xoff + kk2]); \
    } \
    _Pragma("unroll") \
    for (int i = 0; i < 2; i++) { \
        int l = i * 256 + tid; int kk2 = l & 31, j = l >> 5; \
        int jg = j0 + j; \
        const float* wsrc = ((k0) < NX) ? &Wih[(size_t)jg * NX + (k0) + kk2] \
                                        : &Whh[(size_t)jg * ND + (k0) - NX + kk2]; \
        cpa4(&Ws[buf][kk2][j], wsrc); \
    } \
    CP_COMMIT; } while (0)

    GA_LOAD(0, 0);
    ull acc[2] = {};
    for (int c = 0; c < 96; c++) {
        int buf = c & 1;
        if (c + 1 < 96) { GA_LOAD((c + 1) * 32, buf ^ 1); CP_WAIT1; }
        else { CP_WAIT0; }
        __syncthreads();
#pragma unroll
        for (int kk = 0; kk < 32; kk++) {
            float4 a4 = *(const float4*)&Xs[buf][kk][ty * 4];
            ull* ap = (ull*)&a4;
            float w = Ws[buf][kk][tx];
            ull w2 = pack2(w, w);
            fma2(acc[0], ap[0], w2);
            fma2(acc[1], ap[1], w2);
        }
        __syncthreads();
    }
    int j = j0 + tx;
    float bb2 = bih[j] + bhh[j];
#pragma unroll
    for (int p = 0; p < 2; p++) {
        float lo, hi;
        unpack2(acc[p], lo, hi);
        int b0r = ty * 4 + 2 * p;
        g_gates[b0r * (4 * ND) + j] = lo + bb2;
        g_gates[(b0r + 1) * (4 * ND) + j] = hi + bb2;
    }
#undef GA_LOAD
}

__global__ void k_lstmpw(int t, int ph) {
    const int b = blockIdx.x;
    if (t >= g_declen[b]) return;
    const int d = threadIdx.x;
    const float* g = g_gates + b * (4 * ND);
    float i_ = sigf(g[d]);
    float f_ = sigf(g[ND + d]);
    float gg = tanhf(g[2 * ND + d]);
    float o_ = sigf(g[3 * ND + d]);
    float c = f_ * g_c[b * ND + d] + i_ * gg;
    g_c[b * ND + d] = c;
    g_h[ph ^ 1][b * ND + d] = o_ * tanhf(c);
}

// ---------------------------------------------------------------
// fc: preds = h_new @ fc_W + fc_b. 16b x 128v tiles, transposed h staging,
// f32x2 over b-pairs, active-block skip. grid (79, 4).
// ---------------------------------------------------------------
__global__ void k_fc(int t, int ph, const float* __restrict__ Wf, const float* __restrict__ bf,
                     float* __restrict__ out) {
    __shared__ float hs_t[ND][20];
    const int v0 = blockIdx.x * 128;
    const int b0 = blockIdx.y * 16;
    const int tid = threadIdx.x;
    const int v = v0 + (tid & 127);
    const int bg = (tid >> 7) * 8;
    const bool active = (g_declen[b0] > t);   // sorted descending

    if (!active) {
        if (v < NV) {
#pragma unroll
            for (int i = 0; i < 8; i++)
                out[(size_t)((b0 + bg + i) * NT + t) * NV + v] = 0.f;
        }
        return;
    }
    const float* h_new = g_h[ph ^ 1];
    for (int i = tid; i < 16 * ND; i += 256) {
        int b = i >> 9, k = i & 511;
        hs_t[k][b] = h_new[(b0 + b) * ND + k];
    }
    __syncthreads();
    if (v >= NV) return;

    ull acc[4] = {};
    const float* wc = Wf + v;
    for (int k = 0; k < ND; k += 4) {
        float w0 = __ldg(&wc[(size_t)k * NV]);
        float w1 = __ldg(&wc[(size_t)(k + 1) * NV]);
        float w2 = __ldg(&wc[(size_t)(k + 2) * NV]);
        float w3 = __ldg(&wc[(size_t)(k + 3) * NV]);
        ull W0 = pack2(w0, w0), W1 = pack2(w1, w1), W2 = pack2(w2, w2), W3 = pack2(w3, w3);
#pragma unroll
        for (int u = 0; u < 4; u++) {
            ull Wu = (u == 0) ? W0 : (u == 1) ? W1 : (u == 2) ? W2 : W3;
            float4 ha = *(const float4*)&hs_t[k + u][bg];
            float4 hb = *(const float4*)&hs_t[k + u][bg + 4];
            ull* hpa = (ull*)&ha;
            ull* hpb = (ull*)&hb;
            fma2(acc[0], hpa[0], Wu);
            fma2(acc[1], hpa[1], Wu);
            fma2(acc[2], hpb[0], Wu);
            fma2(acc[3], hpb[1], Wu);
        }
    }
    const float bias = bf[v];
#pragma unroll
    for (int p = 0; p < 4; p++) {
        float lo, hi;
        unpack2(acc[p], lo, hi);
        int bA = b0 + bg + 2 * p;
        int bB = bA + 1;
        float rA = (t < g_declen[bA]) ? (lo + bias) : 0.f;
        float rB = (t < g_declen[bB]) ? (hi + bias) : 0.f;
        out[(size_t)(bA * NT + t) * NV + v] = rA;
        out[(size_t)(bB * NT + t) * NV + v] = rB;
    }
}

// ---------------------------------------------------------------
extern "C" void kernel_launch(void* const* d_in, const int* in_sizes, int n_in,
                              void* d_out, int out_size) {
    (void)in_sizes; (void)n_in; (void)out_size;
    const float* enc     = (const float*)d_in[0];
    const int*   caps    = (const int*)d_in[1];
    const int*   clen    = (const int*)d_in[2];
    const float* embW    = (const float*)d_in[3];
    const float* attEncW = (const float*)d_in[4];
    const float* attEncB = (const float*)d_in[5];
    const float* attDecW = (const float*)d_in[6];
    const float* attDecB = (const float*)d_in[7];
    const float* fullW   = (const float*)d_in[8];
    const float* fullB   = (const float*)d_in[9];
    const float* Wih     = (const float*)d_in[10];
    const float* Whh     = (const float*)d_in[11];
    const float* bih     = (const float*)d_in[12];
    const float* bhh     = (const float*)d_in[13];
    const float* iHW     = (const float*)d_in[14];
    const float* iHb     = (const float*)d_in[15];
    const float* iCW     = (const float*)d_in[16];
    const float* iCb     = (const float*)d_in[17];
    const float* fbW     = (const float*)d_in[18];
    const float* fbb     = (const float*)d_in[19];
    const float* fcW     = (const float*)d_in[20];
    const float* fcb     = (const float*)d_in[21];
    float* out = (float*)d_out;

    k_sort<<<1, 64>>>(clen, caps, out);
    k_mean<<<dim3(8, 64), 256>>>(enc);
    k_inithc<<<NB, 256>>>(iHW, iHb, iCW, iCb);
    k_att1<<<dim3(8, 196), 256>>>(enc, attEncW, attEncB);

    for (int t = 0; t < NT; t++) {
        int ph = t & 1;
        k_hproj<<<NX / 16, 256>>>(ph, attDecW, attDecB, fbW, fbb);
        k_alpha<<<NB, 256>>>(t, fullW, fullB, embW, caps, out);
        k_awex<<<dim3(NE / 256, NB), 256>>>(t, enc);
        k_gates<<<(4 * ND) / 16, 256>>>(ph, Wih, Whh, bih, bhh);
        k_lstmpw<<<NB, ND>>>(t, ph);
        k_fc<<<dim3((NV + 127) / 128, 4), 256>>>(t, ph, fcW, fcb, out);
    }
}

// round 5
// speedup vs baseline: 1.6735x; 1.2451x over previous
#include <cuda_runtime.h>
#include <math.h>

#define NB 64
#define NP 196
#define NE 2048
#define ND 512
#define NA 512
#define NEMB 512
#define NV 10000
#define NL 52
#define NT 51
#define NX 2560   // EMB + ENC

// ---- output layout (flattened tuple, float32) ----
#define OUT_PRED   0
#define OUT_CAPS   32640000      // NB*NT*NV
#define OUT_DECLEN 32643328      // + NB*NL
#define OUT_ALPHA  32643392      // + NB
#define OUT_ORDER  33283136      // + NB*NT*NP

typedef unsigned long long ull;

// ---- scratch (device globals; no allocation) ----
__device__ int   g_order[NB];
__device__ int   g_declen[NB];
__device__ float g_att1[(size_t)NB * NP * NA];
__device__ float g_h[2][NB * ND];
__device__ float g_c[NB * ND];
__device__ float g_alpha[NB * NP];
__device__ float g_att2[NB * NA];
__device__ float g_gate[NB * NE];
__device__ float g_awe[NB * NE];                 // gate * attention-weighted enc
__device__ float g_embT[NT][NB][NEMB];           // embeddings for all steps (sorted order)
__device__ float g_gxh_e[NB * 4 * ND];           // Wih-emb part + biases
__device__ float g_gxh_h[NB * 4 * ND];           // Whh part
__device__ float g_gawe[4][NB * 4 * ND];         // Wih-awe part, 4 K-splits
__device__ float g_mean[NB * NE];

__device__ __forceinline__ float sigf(float x) { return 1.f / (1.f + expf(-x)); }

// ---- packed f32x2 FMA helpers ----
__device__ __forceinline__ ull pack2(float x, float y) {
    ull d; asm("mov.b64 %0, {%1, %2};" : "=l"(d) : "f"(x), "f"(y)); return d;
}
__device__ __forceinline__ void fma2(ull& d, ull a, ull b) {
    asm("fma.rn.f32x2 %0, %1, %2, %0;" : "+l"(d) : "l"(a), "l"(b));
}
__device__ __forceinline__ void unpack2(ull v, float& lo, float& hi) {
    asm("mov.b64 {%0, %1}, %2;" : "=f"(lo), "=f"(hi) : "l"(v));
}

// ---- cp.async helpers ----
__device__ __forceinline__ void cpa4(void* dst, const void* src) {
    unsigned sd = (unsigned)__cvta_generic_to_shared(dst);
    asm volatile("cp.async.ca.shared.global [%0], [%1], 4;" :: "r"(sd), "l"(src));
}
#define CP_COMMIT asm volatile("cp.async.commit_group;")
#define CP_WAIT1  asm volatile("cp.async.wait_group 1;")
#define CP_WAIT0  asm volatile("cp.async.wait_group 0;")

// ===============================================================
// Balanced 64x128 GEMM tile, K=512, accumulate into acc.
// 256 threads. Thread (tx=tid&31, ty=tid>>5) owns rows ty*8..+7 (4 f32x2
// pairs) and cols tx, tx+32, tx+64, tx+96 (relative to tile).
// A staged Xs[b][k] (stride 32): global reads coalesced, smem writes
// conflict-free, compute reads warp-uniform broadcast.
// W staged Ws[k][j] (stride 129): conflict-free for both k-major and
// j-major weight layouts; compute reads lane-consecutive.
// wact=false: warp skips all FMAs (uniform branch) but participates in
// loads and barriers.
// ===============================================================
template<bool KMAJOR>
__device__ __forceinline__ void gemm_acc(
    const float* __restrict__ Xg, int xstride,
    const float* __restrict__ Wg, size_t wstride, int vw,
    bool wact, ull acc[4][4], float* Xs, float* Ws, int tid)
{
    const int tx = tid & 31, ty = tid >> 5;
    auto stage = [&](int k0, int st) {
#pragma unroll
        for (int i = 0; i < 8; i++) {                 // X: 64 rows x 32 k
            int idx = (i << 8) + tid;
            int k = idx & 31, b = idx >> 5;
            cpa4(&Xs[st * 2048 + (b << 5) + k], Xg + (size_t)b * xstride + k0 + k);
        }
#pragma unroll
        for (int i = 0; i < 16; i++) {                // W: 32 k x 128 j
            int idx = (i << 8) + tid;
            int j = KMAJOR ? (idx & 127) : (idx >> 5);
            int k = KMAJOR ? (idx >> 7) : (idx & 31);
            int jc = (j < vw) ? j : 0;
            const float* src = KMAJOR ? (Wg + (size_t)(k0 + k) * wstride + jc)
                                      : (Wg + (size_t)jc * wstride + k0 + k);
            cpa4(&Ws[st * 4128 + k * 129 + j], src);
        }
        CP_COMMIT;
    };
    stage(0, 0);
    for (int c = 0; c < 16; c++) {
        int st = c & 1;
        if (c < 15) { stage((c + 1) << 5, st ^ 1); CP_WAIT1; }
        else        { CP_WAIT0; }
        __syncthreads();
        if (wact) {
#pragma unroll
            for (int kk = 0; kk < 32; kk++) {
                ull a[4]; float w[4];
#pragma unroll
                for (int p = 0; p < 4; p++)
                    a[p] = pack2(Xs[st * 2048 + ((ty * 8 + 2 * p) << 5) + kk],
                                 Xs[st * 2048 + ((ty * 8 + 2 * p + 1) << 5) + kk]);
#pragma unroll
                for (int jj = 0; jj < 4; jj++) w[jj] = Ws[st * 4128 + kk * 129 + tx + (jj << 5)];
#pragma unroll
                for (int jj = 0; jj < 4; jj++) {
                    ull w2 = pack2(w[jj], w[jj]);
#pragma unroll
                    for (int p = 0; p < 4; p++) fma2(acc[p][jj], a[p], w2);
                }
            }
        }
        __syncthreads();
    }
}

// ---------------------------------------------------------------
__global__ void k_sort(const int* __restrict__ clen, const int* __restrict__ caps,
                       float* __restrict__ out) {
    int i = threadIdx.x;
    __shared__ int len[NB];
    if (i < NB) len[i] = clen[i];
    __syncthreads();
    if (i < NB) {
        int li = len[i], r = 0;
        for (int j = 0; j < NB; j++) {
            int lj = len[j];
            if (lj > li || (lj == li && j < i)) r++;
        }
        g_order[r] = i;
    }
    __syncthreads();
    if (i < NB) {
        int src = g_order[i];
        int dl = len[src] - 1;
        g_declen[i] = dl;
        out[OUT_DECLEN + i] = (float)dl;
        out[OUT_ORDER + i] = (float)src;
        for (int t = 0; t < NL; t++)
            out[OUT_CAPS + i * NL + t] = (float)caps[src * NL + t];
    }
}

// precompute all embeddings (sorted order): g_embT[t][b][:]
__global__ void k_emb(const int* __restrict__ caps, const float* __restrict__ embW) {
    int t = blockIdx.x, b = blockIdx.y, tid = threadIdx.x;
    int cap = caps[g_order[b] * NL + t];
    for (int i = tid; i < NEMB; i += 128)
        g_embT[t][b][i] = embW[(size_t)cap * NEMB + i];
}

__global__ void k_mean(const float* __restrict__ enc) {
    int b = blockIdx.y;
    int e = blockIdx.x * 256 + threadIdx.x;
    const float* base = enc + (size_t)g_order[b] * NP * NE + e;
    float s = 0.f;
#pragma unroll 7
    for (int p = 0; p < NP; p++) s += base[(size_t)p * NE];
    g_mean[b * NE + e] = s * (1.0f / NP);
}

__global__ void k_inithc(const float* __restrict__ HW, const float* __restrict__ Hb,
                         const float* __restrict__ CW, const float* __restrict__ Cb) {
    int b = blockIdx.x, tid = threadIdx.x;
    __shared__ float m[NE];
    for (int e = tid; e < NE; e += 256) m[e] = g_mean[b * NE + e];
    __syncthreads();
    for (int d = tid; d < ND; d += 256) {
        float sh = 0.f, sc = 0.f;
        for (int e = 0; e < NE; e++) {
            float me = m[e];
            sh += me * HW[(size_t)e * ND + d];
            sc += me * CW[(size_t)e * ND + d];
        }
        g_h[0][b * ND + d] = sh + Hb[d];
        g_c[b * ND + d] = sc + Cb[d];
    }
}

// ---------------------------------------------------------------
// att1 = enc_sorted @ att_enc_W + b : 128m x 128n tiles, K=2048.
// Thread: 16 rows x 4 cols. grid (4, 98). Dynamic smem 65792 B.
// ---------------------------------------------------------------
__global__ __launch_bounds__(256) void k_att1(const float* __restrict__ enc,
                                              const float* __restrict__ W,
                                              const float* __restrict__ bias) {
    extern __shared__ float dyn[];
    float* Xs = dyn;                 // 2 x 128 x 32
    float* Ws = dyn + 2 * 128 * 32;  // 2 x 32 x 129
    __shared__ int rowBase[128];
    const int bn = blockIdx.x, bm = blockIdx.y, tid = threadIdx.x;
    const int row0 = bm * 128;
    if (tid < 128) {
        int m = row0 + tid;
        rowBase[tid] = g_order[m / NP] * NP + (m % NP);
    }
    __syncthreads();
    const int tx = tid & 31, ty = tid >> 5;
    ull acc[8][4] = {};
    auto stage = [&](int k0, int st) {
#pragma unroll
        for (int i = 0; i < 16; i++) {               // 128 x 32
            int idx = (i << 8) + tid;
            int k = idx & 31, m = idx >> 5;
            cpa4(&Xs[st * 4096 + (m << 5) + k], enc + (size_t)rowBase[m] * NE + k0 + k);
        }
#pragma unroll
        for (int i = 0; i < 16; i++) {               // 32 x 128
            int idx = (i << 8) + tid;
            int j = idx & 127, k = idx >> 7;
            cpa4(&Ws[st * 4128 + k * 129 + j], W + (size_t)(k0 + k) * NA + bn * 128 + j);
        }
        CP_COMMIT;
    };
    stage(0, 0);
    for (int c = 0; c < 64; c++) {
        int st = c & 1;
        if (c < 63) { stage((c + 1) << 5, st ^ 1); CP_WAIT1; }
        else        { CP_WAIT0; }
        __syncthreads();
#pragma unroll
        for (int kk = 0; kk < 32; kk++) {
            float w[4]; ull a[8];
#pragma unroll
            for (int jj = 0; jj < 4; jj++) w[jj] = Ws[st * 4128 + kk * 129 + tx + (jj << 5)];
#pragma unroll
            for (int p = 0; p < 8; p++)
                a[p] = pack2(Xs[st * 4096 + ((ty * 16 + 2 * p) << 5) + kk],
                             Xs[st * 4096 + ((ty * 16 + 2 * p + 1) << 5) + kk]);
#pragma unroll
            for (int jj = 0; jj < 4; jj++) {
                ull w2 = pack2(w[jj], w[jj]);
#pragma unroll
                for (int p = 0; p < 8; p++) fma2(acc[p][jj], a[p], w2);
            }
        }
        __syncthreads();
    }
#pragma unroll
    for (int p = 0; p < 8; p++) {
#pragma unroll
        for (int jj = 0; jj < 4; jj++) {
            int col = bn * 128 + tx + (jj << 5);
            float lo, hi; unpack2(acc[p][jj], lo, hi);
            size_t m0 = row0 + ty * 16 + 2 * p;
            float bv = bias[col];
            g_att1[m0 * NA + col] = lo + bv;
            g_att1[(m0 + 1) * NA + col] = hi + bv;
        }
    }
}

// ---------------------------------------------------------------
// k_big: one wave per step.
//   blocks [0,20):   hproj  — att2 = h@attW+b (blk<4), gate = sig(h@fbW+b)
//   blocks [20,36):  gates emb part: emb[t] @ Wih[:, :512]^T + biases
//   blocks [36,52):  gates h part:   h @ Whh^T
//   blocks [52,131): fc for step t-1: preds = h @ fcW + b (masked)
// t == NT: only fc section runs (tail).
// ---------------------------------------------------------------
__global__ __launch_bounds__(256) void k_big(int t,
        const float* __restrict__ attW, const float* __restrict__ attb,
        const float* __restrict__ fbW,  const float* __restrict__ fbb,
        const float* __restrict__ Wih,  const float* __restrict__ Whh,
        const float* __restrict__ bih,  const float* __restrict__ bhh,
        const float* __restrict__ fcW,  const float* __restrict__ fcb,
        float* __restrict__ out) {
    extern __shared__ float dyn[];
    float* Xs = dyn;                // 2 x 64 x 32
    float* Ws = dyn + 2 * 64 * 32;  // 2 x 32 x 129
    const int bx = blockIdx.x, tid = threadIdx.x;
    const int tx = tid & 31, ty = tid >> 5;
    const int ph = t & 1;
    const float* h = g_h[ph];
    const int tprev = t - 1;
    ull acc[4][4] = {};

    if (bx < 52) {
        if (t >= NT) return;
        const bool wact = (t < g_declen[ty * 8]);
        if (bx < 20) {
            // ---- hproj ----
            int j0 = bx * 128;
            if (bx < 4) {
                gemm_acc<true>(h, ND, attW + j0, NA, 128, wact, acc, Xs, Ws, tid);
                if (wact) {
#pragma unroll
                    for (int p = 0; p < 4; p++) {
                        int b0r = ty * 8 + 2 * p;
#pragma unroll
                        for (int jj = 0; jj < 4; jj++) {
                            int col = j0 + tx + (jj << 5);
                            float lo, hi; unpack2(acc[p][jj], lo, hi);
                            float bv = attb[col];
                            g_att2[b0r * NA + col] = lo + bv;
                            g_att2[(b0r + 1) * NA + col] = hi + bv;
                        }
                    }
                }
            } else {
                int jj0 = j0 - 512;
                gemm_acc<true>(h, ND, fbW + jj0, NE, 128, wact, acc, Xs, Ws, tid);
                if (wact) {
#pragma unroll
                    for (int p = 0; p < 4; p++) {
                        int b0r = ty * 8 + 2 * p;
#pragma unroll
                        for (int jj = 0; jj < 4; jj++) {
                            int e = jj0 + tx + (jj << 5);
                            float lo, hi; unpack2(acc[p][jj], lo, hi);
                            float bv = fbb[e];
                            g_gate[b0r * NE + e] = sigf(lo + bv);
                            g_gate[(b0r + 1) * NE + e] = sigf(hi + bv);
                        }
                    }
                }
            }
        } else if (bx < 36) {
            // ---- gates emb part ----
            int j0 = (bx - 20) * 128;
            gemm_acc<false>(&g_embT[t][0][0], NEMB, Wih + (size_t)j0 * NX, NX, 128,
                            wact, acc, Xs, Ws, tid);
            if (wact) {
#pragma unroll
                for (int p = 0; p < 4; p++) {
                    int b0r = ty * 8 + 2 * p;
#pragma unroll
                    for (int jj = 0; jj < 4; jj++) {
                        int j = j0 + tx + (jj << 5);
                        float lo, hi; unpack2(acc[p][jj], lo, hi);
                        float bv = bih[j] + bhh[j];
                        g_gxh_e[b0r * (4 * ND) + j] = lo + bv;
                        g_gxh_e[(b0r + 1) * (4 * ND) + j] = hi + bv;
                    }
                }
            }
        } else {
            // ---- gates h part ----
            int j0 = (bx - 36) * 128;
            gemm_acc<false>(h, ND, Whh + (size_t)j0 * ND, ND, 128,
                            wact, acc, Xs, Ws, tid);
            if (wact) {
#pragma unroll
                for (int p = 0; p < 4; p++) {
                    int b0r = ty * 8 + 2 * p;
#pragma unroll
                    for (int jj = 0; jj < 4; jj++) {
                        int j = j0 + tx + (jj << 5);
                        float lo, hi; unpack2(acc[p][jj], lo, hi);
                        g_gxh_h[b0r * (4 * ND) + j] = lo;
                        g_gxh_h[(b0r + 1) * (4 * ND) + j] = hi;
                    }
                }
            }
        }
    } else {
        // ---- fc for tprev ----
        if (tprev < 0) return;
        const bool wact = (tprev < g_declen[ty * 8]);
        int j0 = (bx - 52) * 128;
        int vw = NV - j0; if (vw > 128) vw = 128;
        gemm_acc<true>(h, ND, fcW + j0, NV, vw, wact, acc, Xs, Ws, tid);
#pragma unroll
        for (int p = 0; p < 4; p++) {
            int bA = ty * 8 + 2 * p, bB = bA + 1;
            bool actA = tprev < g_declen[bA];
            bool actB = tprev < g_declen[bB];
#pragma unroll
            for (int jj = 0; jj < 4; jj++) {
                int v = j0 + tx + (jj << 5);
                if (v < NV) {
                    float lo, hi; unpack2(acc[p][jj], lo, hi);
                    float bv = fcb[v];
                    out[OUT_PRED + (size_t)(bA * NT + tprev) * NV + v] = actA ? lo + bv : 0.f;
                    out[OUT_PRED + (size_t)(bB * NT + tprev) * NV + v] = actB ? hi + bv : 0.f;
                }
            }
        }
    }
}

// ---------------------------------------------------------------
// alpha: e = relu(att1+att2)@w + b, softmax over pixels
// ---------------------------------------------------------------
__global__ void k_alpha(int t, const float* __restrict__ fullw, const float* __restrict__ fullb,
                        float* __restrict__ out) {
    const int b = blockIdx.x, tid = threadIdx.x;
    const int warp = tid >> 5, lane = tid & 31;
    float* aout = out + OUT_ALPHA + ((size_t)b * NT + t) * NP;
    if (t >= g_declen[b]) {
        for (int p = tid; p < NP; p += 256) aout[p] = 0.f;
        return;
    }
    __shared__ float att2s[NA];
    __shared__ float ws[NA];
    __shared__ float ev[NP];
    __shared__ float red[8];
    __shared__ float smax, ssum;
    for (int i = tid; i < NA; i += 256) { att2s[i] = g_att2[b * NA + i]; ws[i] = fullw[i]; }
    __syncthreads();
    const float fb = fullb[0];
    for (int p = warp; p < NP; p += 8) {
        const float* a1 = g_att1 + ((size_t)(b * NP + p)) * NA;
        float s = 0.f;
#pragma unroll 4
        for (int a = lane; a < NA; a += 32) {
            float v = a1[a] + att2s[a];
            s += fmaxf(v, 0.f) * ws[a];
        }
#pragma unroll
        for (int o = 16; o; o >>= 1) s += __shfl_xor_sync(0xffffffffu, s, o);
        if (lane == 0) ev[p] = s + fb;
    }
    __syncthreads();
    float v = (tid < NP) ? ev[tid] : -3.0e38f;
    float m = v;
#pragma unroll
    for (int o = 16; o; o >>= 1) m = fmaxf(m, __shfl_xor_sync(0xffffffffu, m, o));
    if (lane == 0) red[warp] = m;
    __syncthreads();
    if (tid == 0) { float mm = red[0]; for (int i = 1; i < 8; i++) mm = fmaxf(mm, red[i]); smax = mm; }
    __syncthreads();
    float ex = (tid < NP) ? expf(v - smax) : 0.f;
    float s2 = ex;
#pragma unroll
    for (int o = 16; o; o >>= 1) s2 += __shfl_xor_sync(0xffffffffu, s2, o);
    if (lane == 0) red[warp] = s2;
    __syncthreads();
    if (tid == 0) { float ss = 0.f; for (int i = 0; i < 8; i++) ss += red[i]; ssum = ss; }
    __syncthreads();
    if (tid < NP) {
        float a = ex / ssum;
        g_alpha[b * NP + tid] = a;
        aout[tid] = a;
    }
}

// ---------------------------------------------------------------
// awex: g_awe[b][e] = gate[b][e] * sum_p alpha_p enc[b,p,e]
// ---------------------------------------------------------------
__global__ void k_awex(int t, const float* __restrict__ enc) {
    const int b = blockIdx.y;
    if (t >= g_declen[b]) return;
    const int tid = threadIdx.x;
    const int e = blockIdx.x * 256 + tid;
    __shared__ float al[NP];
    for (int i = tid; i < NP; i += 256) al[i] = g_alpha[b * NP + i];
    __syncthreads();
    const float* eb = enc + ((size_t)g_order[b] * NP) * NE + e;
    float awe = 0.f;
#pragma unroll 7
    for (int p = 0; p < NP; p++) awe += al[p] * eb[(size_t)p * NE];
    g_awe[b * NE + e] = g_gate[b * NE + e] * awe;
}

// ---------------------------------------------------------------
// gates awe part: g_gawe[ks] = awe[:, ks*512:(ks+1)*512] @ Wih[:, 512+ks*512 ...]^T
// grid (16 j-tiles, 4 k-splits)
// ---------------------------------------------------------------
__global__ __launch_bounds__(256) void k_gawe(int t, const float* __restrict__ Wih) {
    extern __shared__ float dyn[];
    float* Xs = dyn;
    float* Ws = dyn + 2 * 64 * 32;
    const int tid = threadIdx.x;
    const int tx = tid & 31, ty = tid >> 5;
    const int j0 = blockIdx.x * 128;
    const int ks = blockIdx.y;
    const bool wact = (t < g_declen[ty * 8]);
    ull acc[4][4] = {};
    gemm_acc<false>(g_awe + ks * 512, NE, Wih + (size_t)j0 * NX + 512 + ks * 512, NX, 128,
                    wact, acc, Xs, Ws, tid);
    if (wact) {
#pragma unroll
        for (int p = 0; p < 4; p++) {
            int b0r = ty * 8 + 2 * p;
#pragma unroll
            for (int jj = 0; jj < 4; jj++) {
                int j = j0 + tx + (jj << 5);
                float lo, hi; unpack2(acc[p][jj], lo, hi);
                g_gawe[ks][b0r * (4 * ND) + j] = lo;
                g_gawe[ks][(b0r + 1) * (4 * ND) + j] = hi;
            }
        }
    }
}

// LSTM pointwise: sum the 6 gate partials, update c/h (active rows only)
__global__ void k_lstmpw(int t, int ph) {
    const int b = blockIdx.x;
    if (t >= g_declen[b]) return;
    const int d = threadIdx.x;
    float gv[4];
#pragma unroll
    for (int q = 0; q < 4; q++) {
        int j = q * ND + d;
        float s = g_gxh_e[b * (4 * ND) + j] + g_gxh_h[b * (4 * ND) + j];
#pragma unroll
        for (int ks = 0; ks < 4; ks++) s += g_gawe[ks][b * (4 * ND) + j];
        gv[q] = s;
    }
    float i_ = sigf(gv[0]);
    float f_ = sigf(gv[1]);
    float gg = tanhf(gv[2]);
    float o_ = sigf(gv[3]);
    float c = f_ * g_c[b * ND + d] + i_ * gg;
    g_c[b * ND + d] = c;
    g_h[ph ^ 1][b * ND + d] = o_ * tanhf(c);
}

// ---------------------------------------------------------------
extern "C" void kernel_launch(void* const* d_in, const int* in_sizes, int n_in,
                              void* d_out, int out_size) {
    (void)in_sizes; (void)n_in; (void)out_size;
    const float* enc     = (const float*)d_in[0];
    const int*   caps    = (const int*)d_in[1];
    const int*   clen    = (const int*)d_in[2];
    const float* embW    = (const float*)d_in[3];
    const float* attEncW = (const float*)d_in[4];
    const float* attEncB = (const float*)d_in[5];
    const float* attDecW = (const float*)d_in[6];
    const float* attDecB = (const float*)d_in[7];
    const float* fullW   = (const float*)d_in[8];
    const float* fullB   = (const float*)d_in[9];
    const float* Wih     = (const float*)d_in[10];
    const float* Whh     = (const float*)d_in[11];
    const float* bih     = (const float*)d_in[12];
    const float* bhh     = (const float*)d_in[13];
    const float* iHW     = (const float*)d_in[14];
    const float* iHb     = (const float*)d_in[15];
    const float* iCW     = (const float*)d_in[16];
    const float* iCb     = (const float*)d_in[17];
    const float* fbW     = (const float*)d_in[18];
    const float* fbb     = (const float*)d_in[19];
    const float* fcW     = (const float*)d_in[20];
    const float* fcb     = (const float*)d_in[21];
    float* out = (float*)d_out;

    const int SM_STEP = (2 * 64 * 32 + 2 * 32 * 129) * 4;    // 49408
    const int SM_ATT1 = (2 * 128 * 32 + 2 * 32 * 129) * 4;   // 65792
    cudaFuncSetAttribute(k_big,  cudaFuncAttributeMaxDynamicSharedMemorySize, SM_STEP);
    cudaFuncSetAttribute(k_gawe, cudaFuncAttributeMaxDynamicSharedMemorySize, SM_STEP);
    cudaFuncSetAttribute(k_att1, cudaFuncAttributeMaxDynamicSharedMemorySize, SM_ATT1);

    k_sort<<<1, 64>>>(clen, caps, out);
    k_emb<<<dim3(NT, NB), 128>>>(caps, embW);
    k_mean<<<dim3(8, 64), 256>>>(enc);
    k_inithc<<<NB, 256>>>(iHW, iHb, iCW, iCb);
    k_att1<<<dim3(4, 98), 256, SM_ATT1>>>(enc, attEncW, attEncB);

    for (int t = 0; t < NT; t++) {
        k_big<<<131, 256, SM_STEP>>>(t, attDecW, attDecB, fbW, fbb,
                                     Wih, Whh, bih, bhh, fcW, fcb, out);
        k_alpha<<<NB, 256>>>(t, fullW, fullB, out);
        k_awex<<<dim3(NE / 256, NB), 256>>>(t, enc);
        k_gawe<<<dim3(16, 4), 256, SM_STEP>>>(t, Wih);
        k_lstmpw<<<NB, ND>>>(t, t & 1);
    }
    // fc tail for the last step
    k_big<<<131, 256, SM_STEP>>>(NT, attDecW, attDecB, fbW, fbb,
                                 Wih, Whh, bih, bhh, fcW, fcb, out);
}

// round 6
// speedup vs baseline: 1.7099x; 1.0218x over previous
#include <cuda_runtime.h>
#include <math.h>

#define NB 64
#define NP 196
#define NE 2048
#define ND 512
#define NA 512
#define NEMB 512
#define NV 10000
#define NL 52
#define NT 51
#define NX 2560   // EMB + ENC

// ---- output layout (flattened tuple, float32) ----
#define OUT_PRED   0
#define OUT_CAPS   32640000      // NB*NT*NV
#define OUT_DECLEN 32643328      // + NB*NL
#define OUT_ALPHA  32643392      // + NB
#define OUT_ORDER  33283136      // + NB*NT*NP

typedef unsigned long long ull;

// ---- scratch (device globals; no allocation) ----
__device__ int   g_order[NB];
__device__ int   g_declen[NB];
__device__ float g_att1[(size_t)NB * NP * NA];
__device__ float g_h[2][NB * ND];
__device__ float g_c[NB * ND];
__device__ float g_att2[NB * NA];
__device__ float g_gate[NB * NE];
__device__ float g_awe[NB * NE];
__device__ float g_embT[NT][NB][NEMB];
__device__ float g_gxh_e[NB * 4 * ND];
__device__ float g_gxh_h[NB * 4 * ND];
__device__ float g_gawe[4][NB * 4 * ND];
__device__ float g_mean[NB * NE];
__device__ float g_initp[4][NB * 1024];

__device__ __forceinline__ float sigf(float x) { return 1.f / (1.f + expf(-x)); }

__device__ __forceinline__ ull pack2(float x, float y) {
    ull d; asm("mov.b64 %0, {%1, %2};" : "=l"(d) : "f"(x), "f"(y)); return d;
}
__device__ __forceinline__ void fma2(ull& d, ull a, ull b) {
    asm("fma.rn.f32x2 %0, %1, %2, %0;" : "+l"(d) : "l"(a), "l"(b));
}
__device__ __forceinline__ void unpack2(ull v, float& lo, float& hi) {
    asm("mov.b64 {%0, %1}, %2;" : "=f"(lo), "=f"(hi) : "l"(v));
}
__device__ __forceinline__ void cpa4(void* dst, const void* src) {
    unsigned sd = (unsigned)__cvta_generic_to_shared(dst);
    asm volatile("cp.async.ca.shared.global [%0], [%1], 4;" :: "r"(sd), "l"(src));
}
#define CP_COMMIT asm volatile("cp.async.commit_group;")
#define CP_WAIT1  asm volatile("cp.async.wait_group 1;")
#define CP_WAIT0  asm volatile("cp.async.wait_group 0;")

// ===============================================================
// 64b x 128j GEMM tile, K = NCH*32, accumulate.
// 256 threads; thread (tx, ty): rows ty*8..+7 (4 f32x2 pairs),
// cols tx*4..tx*4+3 (adjacent -> LDS.128 / STG.128).
// Xs layout [k][68] (b index), Ws [k][132] (j index).
// Inner kk: 2x LDS.128 broadcast (X) + 1x LDS.128 (W) + 16 fma2.
// ===============================================================
#define XS_ST 2176   // 32*68
#define WS_ST 4224   // 32*132
template<bool KMAJOR, int NCH>
__device__ __forceinline__ void gemm_acc(
    const float* __restrict__ Xg, int xstride,
    const float* __restrict__ Wg, size_t wstride, int vw,
    bool wact, ull acc[4][4], float* Xs, float* Ws, int tid)
{
    const int tx = tid & 31, ty = tid >> 5;
    auto stage = [&](int k0, int st) {
#pragma unroll
        for (int i = 0; i < 8; i++) {                 // X: 32k x 64b
            int idx = (i << 8) + tid;
            int k = idx & 31, b = idx >> 5;
            cpa4(&Xs[st * XS_ST + k * 68 + b], Xg + (size_t)b * xstride + k0 + k);
        }
#pragma unroll
        for (int i = 0; i < 16; i++) {                // W: 32k x 128j
            int idx = (i << 8) + tid;
            int j = KMAJOR ? (idx & 127) : (idx >> 5);
            int k = KMAJOR ? (idx >> 7) : (idx & 31);
            int jc = (j < vw) ? j : 0;
            const float* src = KMAJOR ? (Wg + (size_t)(k0 + k) * wstride + jc)
                                      : (Wg + (size_t)jc * wstride + k0 + k);
            cpa4(&Ws[st * WS_ST + k * 132 + j], src);
        }
        CP_COMMIT;
    };
    stage(0, 0);
    for (int c = 0; c < NCH; c++) {
        int st = c & 1;
        if (c < NCH - 1) { stage((c + 1) << 5, st ^ 1); CP_WAIT1; }
        else            { CP_WAIT0; }
        __syncthreads();
        if (wact) {
#pragma unroll
            for (int kk = 0; kk < 32; kk++) {
                const float4 xa = *(const float4*)(Xs + st * XS_ST + kk * 68 + ty * 8);
                const float4 xb = *(const float4*)(Xs + st * XS_ST + kk * 68 + ty * 8 + 4);
                const float4 wv = *(const float4*)(Ws + st * WS_ST + kk * 132 + tx * 4);
                ull a0 = ((const ull*)&xa)[0], a1 = ((const ull*)&xa)[1];
                ull a2 = ((const ull*)&xb)[0], a3 = ((const ull*)&xb)[1];
                ull w0 = pack2(wv.x, wv.x), w1 = pack2(wv.y, wv.y);
                ull w2 = pack2(wv.z, wv.z), w3 = pack2(wv.w, wv.w);
                fma2(acc[0][0], a0, w0); fma2(acc[0][1], a0, w1);
                fma2(acc[0][2], a0, w2); fma2(acc[0][3], a0, w3);
                fma2(acc[1][0], a1, w0); fma2(acc[1][1], a1, w1);
                fma2(acc[1][2], a1, w2); fma2(acc[1][3], a1, w3);
                fma2(acc[2][0], a2, w0); fma2(acc[2][1], a2, w1);
                fma2(acc[2][2], a2, w2); fma2(acc[2][3], a2, w3);
                fma2(acc[3][0], a3, w0); fma2(acc[3][1], a3, w1);
                fma2(acc[3][2], a3, w2); fma2(acc[3][3], a3, w3);
            }
        }
        __syncthreads();
    }
}

// ---------------------------------------------------------------
__global__ void k_sort(const int* __restrict__ clen, const int* __restrict__ caps,
                       float* __restrict__ out) {
    int i = threadIdx.x;
    __shared__ int len[NB];
    if (i < NB) len[i] = clen[i];
    __syncthreads();
    if (i < NB) {
        int li = len[i], r = 0;
        for (int j = 0; j < NB; j++) {
            int lj = len[j];
            if (lj > li || (lj == li && j < i)) r++;
        }
        g_order[r] = i;
    }
    __syncthreads();
    if (i < NB) {
        int src = g_order[i];
        int dl = len[src] - 1;
        g_declen[i] = dl;
        out[OUT_DECLEN + i] = (float)dl;
        out[OUT_ORDER + i] = (float)src;
        for (int t = 0; t < NL; t++)
            out[OUT_CAPS + i * NL + t] = (float)caps[src * NL + t];
    }
}

__global__ void k_emb(const int* __restrict__ caps, const float* __restrict__ embW) {
    int t = blockIdx.x, b = blockIdx.y, tid = threadIdx.x;
    int cap = caps[g_order[b] * NL + t];
    for (int i = tid; i < NEMB; i += 128)
        g_embT[t][b][i] = embW[(size_t)cap * NEMB + i];
}

__global__ void k_mean(const float* __restrict__ enc) {
    int b = blockIdx.y;
    int e = blockIdx.x * 256 + threadIdx.x;
    const float* base = enc + (size_t)g_order[b] * NP * NE + e;
    float s = 0.f;
#pragma unroll 7
    for (int p = 0; p < NP; p++) s += base[(size_t)p * NE];
    g_mean[b * NE + e] = s * (1.0f / NP);
}

// h0/c0 as split-K GEMM: grid (8 j-tiles over 1024 cols, 4 k-splits)
__global__ __launch_bounds__(256) void k_initg(const float* __restrict__ HW,
                                               const float* __restrict__ CW) {
    extern __shared__ float dyn[];
    float* Xs = dyn;
    float* Ws = dyn + 2 * XS_ST;
    const int tid = threadIdx.x;
    const int tx = tid & 31, ty = tid >> 5;
    const int j0 = blockIdx.x * 128;
    const int ks = blockIdx.y;
    const float* W = (j0 < 512) ? (HW + j0) : (CW + j0 - 512);
    ull acc[4][4] = {};
    gemm_acc<true, 16>(g_mean + ks * 512, NE, W + (size_t)ks * 512 * ND, ND, 128,
                       true, acc, Xs, Ws, tid);
#pragma unroll
    for (int p = 0; p < 4; p++) {
        int b0r = ty * 8 + 2 * p;
        float4 lov, hiv;
        unpack2(acc[p][0], lov.x, hiv.x); unpack2(acc[p][1], lov.y, hiv.y);
        unpack2(acc[p][2], lov.z, hiv.z); unpack2(acc[p][3], lov.w, hiv.w);
        *(float4*)&g_initp[ks][b0r * 1024 + j0 + tx * 4] = lov;
        *(float4*)&g_initp[ks][(b0r + 1) * 1024 + j0 + tx * 4] = hiv;
    }
}
__global__ void k_initc(const float* __restrict__ Hb, const float* __restrict__ Cb) {
    int b = blockIdx.x, tid = threadIdx.x;
    for (int j = tid; j < 1024; j += 256) {
        float s = g_initp[0][b * 1024 + j] + g_initp[1][b * 1024 + j]
                + g_initp[2][b * 1024 + j] + g_initp[3][b * 1024 + j];
        if (j < 512) g_h[0][b * ND + j] = s + Hb[j];
        else         g_c[b * ND + j - 512] = s + Cb[j - 512];
    }
}

// ---------------------------------------------------------------
// att1: 128m x 128n tiles, K=2048. Thread: 16 rows x 4 adjacent cols.
// ---------------------------------------------------------------
#define AXS_ST 4224  // 32*132
__global__ __launch_bounds__(256) void k_att1(const float* __restrict__ enc,
                                              const float* __restrict__ W,
                                              const float* __restrict__ bias) {
    extern __shared__ float dyn[];
    float* Xs = dyn;                  // 2 x 32 x 132 (m index)
    float* Ws = dyn + 2 * AXS_ST;     // 2 x 32 x 132 (j index)
    __shared__ int rowBase[128];
    const int bn = blockIdx.x, bm = blockIdx.y, tid = threadIdx.x;
    const int row0 = bm * 128;
    if (tid < 128) {
        int m = row0 + tid;
        rowBase[tid] = g_order[m / NP] * NP + (m % NP);
    }
    __syncthreads();
    const int tx = tid & 31, ty = tid >> 5;
    ull acc[8][4] = {};
    auto stage = [&](int k0, int st) {
#pragma unroll
        for (int i = 0; i < 16; i++) {
            int idx = (i << 8) + tid;
            int k = idx & 31, m = idx >> 5;
            cpa4(&Xs[st * AXS_ST + k * 132 + m], enc + (size_t)rowBase[m] * NE + k0 + k);
        }
#pragma unroll
        for (int i = 0; i < 16; i++) {
            int idx = (i << 8) + tid;
            int j = idx & 127, k = idx >> 7;
            cpa4(&Ws[st * AXS_ST + k * 132 + j], W + (size_t)(k0 + k) * NA + bn * 128 + j);
        }
        CP_COMMIT;
    };
    stage(0, 0);
    for (int c = 0; c < 64; c++) {
        int st = c & 1;
        if (c < 63) { stage((c + 1) << 5, st ^ 1); CP_WAIT1; }
        else        { CP_WAIT0; }
        __syncthreads();
#pragma unroll
        for (int kk = 0; kk < 32; kk++) {
            const float* xrow = Xs + st * AXS_ST + kk * 132 + ty * 16;
            const float4 x0 = *(const float4*)(xrow);
            const float4 x1 = *(const float4*)(xrow + 4);
            const float4 x2 = *(const float4*)(xrow + 8);
            const float4 x3 = *(const float4*)(xrow + 12);
            const float4 wv = *(const float4*)(Ws + st * AXS_ST + kk * 132 + tx * 4);
            ull a[8];
            a[0] = ((const ull*)&x0)[0]; a[1] = ((const ull*)&x0)[1];
            a[2] = ((const ull*)&x1)[0]; a[3] = ((const ull*)&x1)[1];
            a[4] = ((const ull*)&x2)[0]; a[5] = ((const ull*)&x2)[1];
            a[6] = ((const ull*)&x3)[0]; a[7] = ((const ull*)&x3)[1];
            ull w0 = pack2(wv.x, wv.x), w1 = pack2(wv.y, wv.y);
            ull w2 = pack2(wv.z, wv.z), w3 = pack2(wv.w, wv.w);
#pragma unroll
            for (int p = 0; p < 8; p++) {
                fma2(acc[p][0], a[p], w0); fma2(acc[p][1], a[p], w1);
                fma2(acc[p][2], a[p], w2); fma2(acc[p][3], a[p], w3);
            }
        }
        __syncthreads();
    }
    const float4 bv = *(const float4*)&bias[bn * 128 + tx * 4];
#pragma unroll
    for (int p = 0; p < 8; p++) {
        float4 lov, hiv;
        unpack2(acc[p][0], lov.x, hiv.x); unpack2(acc[p][1], lov.y, hiv.y);
        unpack2(acc[p][2], lov.z, hiv.z); unpack2(acc[p][3], lov.w, hiv.w);
        lov.x += bv.x; lov.y += bv.y; lov.z += bv.z; lov.w += bv.w;
        hiv.x += bv.x; hiv.y += bv.y; hiv.z += bv.z; hiv.w += bv.w;
        size_t m0 = row0 + ty * 16 + 2 * p;
        *(float4*)&g_att1[m0 * NA + bn * 128 + tx * 4] = lov;
        *(float4*)&g_att1[(m0 + 1) * NA + bn * 128 + tx * 4] = hiv;
    }
}

// ---------------------------------------------------------------
// k_big: blocks [0,4) att2; [4,20) gate; [20,36) gates-emb; [36,52) gates-h;
// [52,131) fc for step t-1. t==NT: fc only.
// ---------------------------------------------------------------
__global__ __launch_bounds__(256) void k_big(int t,
        const float* __restrict__ attW, const float* __restrict__ attb,
        const float* __restrict__ fbW,  const float* __restrict__ fbb,
        const float* __restrict__ Wih,  const float* __restrict__ Whh,
        const float* __restrict__ bih,  const float* __restrict__ bhh,
        const float* __restrict__ fcW,  const float* __restrict__ fcb,
        float* __restrict__ out) {
    extern __shared__ float dyn[];
    float* Xs = dyn;
    float* Ws = dyn + 2 * XS_ST;
    const int bx = blockIdx.x, tid = threadIdx.x;
    const int tx = tid & 31, ty = tid >> 5;
    const float* h = g_h[t & 1];
    const int tprev = t - 1;
    ull acc[4][4] = {};

    if (bx < 52) {
        if (t >= NT) return;
        const bool wact = (t < g_declen[ty * 8]);
        if (bx < 4) {
            int j0 = bx * 128;
            gemm_acc<true, 16>(h, ND, attW + j0, NA, 128, wact, acc, Xs, Ws, tid);
            if (wact) {
                const float4 bv = *(const float4*)&attb[j0 + tx * 4];
#pragma unroll
                for (int p = 0; p < 4; p++) {
                    int b0r = ty * 8 + 2 * p;
                    float4 lov, hiv;
                    unpack2(acc[p][0], lov.x, hiv.x); unpack2(acc[p][1], lov.y, hiv.y);
                    unpack2(acc[p][2], lov.z, hiv.z); unpack2(acc[p][3], lov.w, hiv.w);
                    lov.x += bv.x; lov.y += bv.y; lov.z += bv.z; lov.w += bv.w;
                    hiv.x += bv.x; hiv.y += bv.y; hiv.z += bv.z; hiv.w += bv.w;
                    *(float4*)&g_att2[b0r * NA + j0 + tx * 4] = lov;
                    *(float4*)&g_att2[(b0r + 1) * NA + j0 + tx * 4] = hiv;
                }
            }
        } else if (bx < 20) {
            int jj0 = (bx - 4) * 128;
            gemm_acc<true, 16>(h, ND, fbW + jj0, NE, 128, wact, acc, Xs, Ws, tid);
            if (wact) {
                const float4 bv = *(const float4*)&fbb[jj0 + tx * 4];
#pragma unroll
                for (int p = 0; p < 4; p++) {
                    int b0r = ty * 8 + 2 * p;
                    float4 lov, hiv;
                    unpack2(acc[p][0], lov.x, hiv.x); unpack2(acc[p][1], lov.y, hiv.y);
                    unpack2(acc[p][2], lov.z, hiv.z); unpack2(acc[p][3], lov.w, hiv.w);
                    lov.x = sigf(lov.x + bv.x); lov.y = sigf(lov.y + bv.y);
                    lov.z = sigf(lov.z + bv.z); lov.w = sigf(lov.w + bv.w);
                    hiv.x = sigf(hiv.x + bv.x); hiv.y = sigf(hiv.y + bv.y);
                    hiv.z = sigf(hiv.z + bv.z); hiv.w = sigf(hiv.w + bv.w);
                    *(float4*)&g_gate[b0r * NE + jj0 + tx * 4] = lov;
                    *(float4*)&g_gate[(b0r + 1) * NE + jj0 + tx * 4] = hiv;
                }
            }
        } else if (bx < 36) {
            int j0 = (bx - 20) * 128;
            gemm_acc<false, 16>(&g_embT[t][0][0], NEMB, Wih + (size_t)j0 * NX, NX, 128,
                                wact, acc, Xs, Ws, tid);
            if (wact) {
                const float4 b1 = *(const float4*)&bih[j0 + tx * 4];
                const float4 b2 = *(const float4*)&bhh[j0 + tx * 4];
#pragma unroll
                for (int p = 0; p < 4; p++) {
                    int b0r = ty * 8 + 2 * p;
                    float4 lov, hiv;
                    unpack2(acc[p][0], lov.x, hiv.x); unpack2(acc[p][1], lov.y, hiv.y);
                    unpack2(acc[p][2], lov.z, hiv.z); unpack2(acc[p][3], lov.w, hiv.w);
                    lov.x += b1.x + b2.x; lov.y += b1.y + b2.y;
                    lov.z += b1.z + b2.z; lov.w += b1.w + b2.w;
                    hiv.x += b1.x + b2.x; hiv.y += b1.y + b2.y;
                    hiv.z += b1.z + b2.z; hiv.w += b1.w + b2.w;
                    *(float4*)&g_gxh_e[b0r * (4 * ND) + j0 + tx * 4] = lov;
                    *(float4*)&g_gxh_e[(b0r + 1) * (4 * ND) + j0 + tx * 4] = hiv;
                }
            }
        } else {
            int j0 = (bx - 36) * 128;
            gemm_acc<false, 16>(h, ND, Whh + (size_t)j0 * ND, ND, 128,
                                wact, acc, Xs, Ws, tid);
            if (wact) {
#pragma unroll
                for (int p = 0; p < 4; p++) {
                    int b0r = ty * 8 + 2 * p;
                    float4 lov, hiv;
                    unpack2(acc[p][0], lov.x, hiv.x); unpack2(acc[p][1], lov.y, hiv.y);
                    unpack2(acc[p][2], lov.z, hiv.z); unpack2(acc[p][3], lov.w, hiv.w);
                    *(float4*)&g_gxh_h[b0r * (4 * ND) + j0 + tx * 4] = lov;
                    *(float4*)&g_gxh_h[(b0r + 1) * (4 * ND) + j0 + tx * 4] = hiv;
                }
            }
        }
    } else {
        if (tprev < 0) return;
        const bool wact = (tprev < g_declen[ty * 8]);
        int j0 = (bx - 52) * 128;
        int vw = NV - j0; if (vw > 128) vw = 128;
        gemm_acc<true, 16>(h, ND, fcW + j0, NV, vw, wact, acc, Xs, Ws, tid);
        const bool vec = (j0 + 128 <= NV);
#pragma unroll
        for (int p = 0; p < 4; p++) {
            int bA = ty * 8 + 2 * p, bB = bA + 1;
            bool actA = tprev < g_declen[bA];
            bool actB = tprev < g_declen[bB];
            if (vec) {
                const float4 bv = *(const float4*)&fcb[j0 + tx * 4];
                float4 lov, hiv;
                unpack2(acc[p][0], lov.x, hiv.x); unpack2(acc[p][1], lov.y, hiv.y);
                unpack2(acc[p][2], lov.z, hiv.z); unpack2(acc[p][3], lov.w, hiv.w);
                lov.x = actA ? lov.x + bv.x : 0.f; lov.y = actA ? lov.y + bv.y : 0.f;
                lov.z = actA ? lov.z + bv.z : 0.f; lov.w = actA ? lov.w + bv.w : 0.f;
                hiv.x = actB ? hiv.x + bv.x : 0.f; hiv.y = actB ? hiv.y + bv.y : 0.f;
                hiv.z = actB ? hiv.z + bv.z : 0.f; hiv.w = actB ? hiv.w + bv.w : 0.f;
                *(float4*)&out[OUT_PRED + (size_t)(bA * NT + tprev) * NV + j0 + tx * 4] = lov;
                *(float4*)&out[OUT_PRED + (size_t)(bB * NT + tprev) * NV + j0 + tx * 4] = hiv;
            } else {
#pragma unroll
                for (int jj = 0; jj < 4; jj++) {
                    int v = j0 + tx * 4 + jj;
                    if (v < NV) {
                        float lo, hi; unpack2(acc[p][jj], lo, hi);
                        float bvv = fcb[v];
                        out[OUT_PRED + (size_t)(bA * NT + tprev) * NV + v] = actA ? lo + bvv : 0.f;
                        out[OUT_PRED + (size_t)(bB * NT + tprev) * NV + v] = actB ? hi + bvv : 0.f;
                    }
                }
            }
        }
    }
}

// ---------------------------------------------------------------
// fused alpha + awe: block b. e = relu(att1+att2)@w+b0, softmax,
// then awe[e] = gate[e] * sum_p alpha_p enc[b,p,e].
// ---------------------------------------------------------------
__global__ __launch_bounds__(256) void k_alphaawe(int t, const float* __restrict__ fullw,
                                                  const float* __restrict__ fullb,
                                                  const float* __restrict__ enc,
                                                  float* __restrict__ out) {
    const int b = blockIdx.x, tid = threadIdx.x;
    const int warp = tid >> 5, lane = tid & 31;
    float* aout = out + OUT_ALPHA + ((size_t)b * NT + t) * NP;
    if (t >= g_declen[b]) {
        for (int p = tid; p < NP; p += 256) aout[p] = 0.f;
        return;
    }
    __shared__ float att2s[NA];
    __shared__ float ws[NA];
    __shared__ float ev[NP];
    __shared__ float al[NP + 4];
    __shared__ float red[8];
    __shared__ float smax, ssum;
    for (int i = tid; i < NA; i += 256) { att2s[i] = g_att2[b * NA + i]; ws[i] = fullw[i]; }
    __syncthreads();
    const float fb = fullb[0];
    for (int p = warp; p < NP; p += 8) {
        const float* a1 = g_att1 + ((size_t)(b * NP + p)) * NA;
        float s = 0.f;
#pragma unroll 4
        for (int a = lane; a < NA; a += 32) {
            float v = a1[a] + att2s[a];
            s += fmaxf(v, 0.f) * ws[a];
        }
#pragma unroll
        for (int o = 16; o; o >>= 1) s += __shfl_xor_sync(0xffffffffu, s, o);
        if (lane == 0) ev[p] = s + fb;
    }
    __syncthreads();
    float v = (tid < NP) ? ev[tid] : -3.0e38f;
    float m = v;
#pragma unroll
    for (int o = 16; o; o >>= 1) m = fmaxf(m, __shfl_xor_sync(0xffffffffu, m, o));
    if (lane == 0) red[warp] = m;
    __syncthreads();
    if (tid == 0) { float mm = red[0]; for (int i = 1; i < 8; i++) mm = fmaxf(mm, red[i]); smax = mm; }
    __syncthreads();
    float ex = (tid < NP) ? expf(v - smax) : 0.f;
    float s2 = ex;
#pragma unroll
    for (int o = 16; o; o >>= 1) s2 += __shfl_xor_sync(0xffffffffu, s2, o);
    if (lane == 0) red[warp] = s2;
    __syncthreads();
    if (tid == 0) { float ss = 0.f; for (int i = 0; i < 8; i++) ss += red[i]; ssum = ss; }
    __syncthreads();
    if (tid < NP) {
        float a = ex / ssum;
        al[tid] = a;
        aout[tid] = a;
    }
    if (tid >= NP && tid < NP + 4) al[tid] = 0.f;   // pad for unroll
    __syncthreads();
    // awe: each thread handles 8 consecutive e
    const int e0 = tid * 8;
    const float* eb = enc + (size_t)g_order[b] * NP * NE + e0;
    float aw[8] = {};
    for (int p = 0; p < 196; p += 2) {
        float a0 = al[p], a1 = al[p + 1];
        const float4 r0a = *(const float4*)(eb + (size_t)p * NE);
        const float4 r0b = *(const float4*)(eb + (size_t)p * NE + 4);
        const float4 r1a = *(const float4*)(eb + (size_t)(p + 1) * NE);
        const float4 r1b = *(const float4*)(eb + (size_t)(p + 1) * NE + 4);
        aw[0] += a0 * r0a.x + a1 * r1a.x; aw[1] += a0 * r0a.y + a1 * r1a.y;
        aw[2] += a0 * r0a.z + a1 * r1a.z; aw[3] += a0 * r0a.w + a1 * r1a.w;
        aw[4] += a0 * r0b.x + a1 * r1b.x; aw[5] += a0 * r0b.y + a1 * r1b.y;
        aw[6] += a0 * r0b.z + a1 * r1b.z; aw[7] += a0 * r0b.w + a1 * r1b.w;
    }
    const float4 g0 = *(const float4*)&g_gate[b * NE + e0];
    const float4 g1 = *(const float4*)&g_gate[b * NE + e0 + 4];
    float4 o0 = {aw[0] * g0.x, aw[1] * g0.y, aw[2] * g0.z, aw[3] * g0.w};
    float4 o1 = {aw[4] * g1.x, aw[5] * g1.y, aw[6] * g1.z, aw[7] * g1.w};
    *(float4*)&g_awe[b * NE + e0] = o0;
    *(float4*)&g_awe[b * NE + e0 + 4] = o1;
}

// ---------------------------------------------------------------
// gates awe part: grid (16 j-tiles, 4 k-splits)
// ---------------------------------------------------------------
__global__ __launch_bounds__(256) void k_gawe(int t, const float* __restrict__ Wih) {
    extern __shared__ float dyn[];
    float* Xs = dyn;
    float* Ws = dyn + 2 * XS_ST;
    const int tid = threadIdx.x;
    const int tx = tid & 31, ty = tid >> 5;
    const int j0 = blockIdx.x * 128;
    const int ks = blockIdx.y;
    const bool wact = (t < g_declen[ty * 8]);
    ull acc[4][4] = {};
    gemm_acc<false, 16>(g_awe + ks * 512, NE, Wih + (size_t)j0 * NX + 512 + ks * 512, NX, 128,
                        wact, acc, Xs, Ws, tid);
    if (wact) {
#pragma unroll
        for (int p = 0; p < 4; p++) {
            int b0r = ty * 8 + 2 * p;
            float4 lov, hiv;
            unpack2(acc[p][0], lov.x, hiv.x); unpack2(acc[p][1], lov.y, hiv.y);
            unpack2(acc[p][2], lov.z, hiv.z); unpack2(acc[p][3], lov.w, hiv.w);
            *(float4*)&g_gawe[ks][b0r * (4 * ND) + j0 + tx * 4] = lov;
            *(float4*)&g_gawe[ks][(b0r + 1) * (4 * ND) + j0 + tx * 4] = hiv;
        }
    }
}

__global__ void k_lstmpw(int t, int ph) {
    const int b = blockIdx.x;
    if (t >= g_declen[b]) return;
    const int d = threadIdx.x;
    float gv[4];
#pragma unroll
    for (int q = 0; q < 4; q++) {
        int j = q * ND + d;
        float s = g_gxh_e[b * (4 * ND) + j] + g_gxh_h[b * (4 * ND) + j];
#pragma unroll
        for (int ks = 0; ks < 4; ks++) s += g_gawe[ks][b * (4 * ND) + j];
        gv[q] = s;
    }
    float i_ = sigf(gv[0]);
    float f_ = sigf(gv[1]);
    float gg = tanhf(gv[2]);
    float o_ = sigf(gv[3]);
    float c = f_ * g_c[b * ND + d] + i_ * gg;
    g_c[b * ND + d] = c;
    g_h[ph ^ 1][b * ND + d] = o_ * tanhf(c);
}

// ---------------------------------------------------------------
extern "C" void kernel_launch(void* const* d_in, const int* in_sizes, int n_in,
                              void* d_out, int out_size) {
    (void)in_sizes; (void)n_in; (void)out_size;
    const float* enc     = (const float*)d_in[0];
    const int*   caps    = (const int*)d_in[1];
    const int*   clen    = (const int*)d_in[2];
    const float* embW    = (const float*)d_in[3];
    const float* attEncW = (const float*)d_in[4];
    const float* attEncB = (const float*)d_in[5];
    const float* attDecW = (const float*)d_in[6];
    const float* attDecB = (const float*)d_in[7];
    const float* fullW   = (const float*)d_in[8];
    const float* fullB   = (const float*)d_in[9];
    const float* Wih     = (const float*)d_in[10];
    const float* Whh     = (const float*)d_in[11];
    const float* bih     = (const float*)d_in[12];
    const float* bhh     = (const float*)d_in[13];
    const float* iHW     = (const float*)d_in[14];
    const float* iHb     = (const float*)d_in[15];
    const float* iCW     = (const float*)d_in[16];
    const float* iCb     = (const float*)d_in[17];
    const float* fbW     = (const float*)d_in[18];
    const float* fbb     = (const float*)d_in[19];
    const float* fcW     = (const float*)d_in[20];
    const float* fcb     = (const float*)d_in[21];
    float* out = (float*)d_out;

    const int SM_STEP = (2 * XS_ST + 2 * WS_ST) * 4;     // 51200
    const int SM_ATT1 = (4 * AXS_ST) * 4;                // 67584
    static int configured = 0;
    if (!configured) {
        cudaFuncSetAttribute(k_big,   cudaFuncAttributeMaxDynamicSharedMemorySize, SM_STEP);
        cudaFuncSetAttribute(k_gawe,  cudaFuncAttributeMaxDynamicSharedMemorySize, SM_STEP);
        cudaFuncSetAttribute(k_initg, cudaFuncAttributeMaxDynamicSharedMemorySize, SM_STEP);
        cudaFuncSetAttribute(k_att1,  cudaFuncAttributeMaxDynamicSharedMemorySize, SM_ATT1);
        configured = 1;
    }

    k_sort<<<1, 64>>>(clen, caps, out);
    k_emb<<<dim3(NT, NB), 128>>>(caps, embW);
    k_mean<<<dim3(8, 64), 256>>>(enc);
    k_initg<<<dim3(8, 4), 256, SM_STEP>>>(iHW, iCW);
    k_initc<<<NB, 256>>>(iHb, iCb);
    k_att1<<<dim3(4, 98), 256, SM_ATT1>>>(enc, attEncW, attEncB);

    for (int t = 0; t < NT; t++) {
        k_big<<<131, 256, SM_STEP>>>(t, attDecW, attDecB, fbW, fbb,
                                     Wih, Whh, bih, bhh, fcW, fcb, out);
        k_alphaawe<<<NB, 256>>>(t, fullW, fullB, enc, out);
        k_gawe<<<dim3(16, 4), 256, SM_STEP>>>(t, Wih);
        k_lstmpw<<<NB, ND>>>(t, t & 1);
    }
    k_big<<<131, 256, SM_STEP>>>(NT, attDecW, attDecB, fbW, fbb,
                                 Wih, Whh, bih, bhh, fcW, fcb, out);
}

// round 7
// speedup vs baseline: 2.3183x; 1.3558x over previous
#include <cuda_runtime.h>
#include <math.h>

#define NB 64
#define NP 196
#define NE 2048
#define ND 512
#define NA 512
#define NEMB 512
#define NV 10000
#define NL 52
#define NT 51
#define NX 2560
#define NBLK 148

#define OUT_PRED   0
#define OUT_CAPS   32640000
#define OUT_DECLEN 32643328
#define OUT_ALPHA  32643392
#define OUT_ORDER  33283136

typedef unsigned long long ull;

// ---- scratch ----
__device__ int   g_order[NB];
__device__ int   g_declen[NB];
__device__ float g_att1[(size_t)NB * NP * NA];
__device__ float g_h[2][NB * ND];
__device__ float g_c[NB * ND];
__device__ float g_att2[NB * NA];
__device__ float g_gate[NB * NE];
__device__ float g_awe[NB * NE];
__device__ float g_embT[NT][NB][NEMB];
__device__ float g_gxh_e[NB * 4 * ND];
__device__ float g_gxh_h[NB * 4 * ND];
__device__ float g_gawe[8][NB * 4 * ND];
__device__ float g_mean[NB * NE];
__device__ float g_initp[4][NB * 1024];

// ---- grid barrier state (self-resetting / monotonic across replays) ----
__device__ unsigned g_cnt;
__device__ volatile unsigned g_gen;
__device__ unsigned g_icnt;

__device__ __forceinline__ float sigf(float x) { return 1.f / (1.f + expf(-x)); }

__device__ __forceinline__ ull pack2(float x, float y) {
    ull d; asm("mov.b64 %0, {%1, %2};" : "=l"(d) : "f"(x), "f"(y)); return d;
}
__device__ __forceinline__ void fma2(ull& d, ull a, ull b) {
    asm("fma.rn.f32x2 %0, %1, %2, %0;" : "+l"(d) : "l"(a), "l"(b));
}
__device__ __forceinline__ void unpack2(ull v, float& lo, float& hi) {
    asm("mov.b64 {%0, %1}, %2;" : "=f"(lo), "=f"(hi) : "l"(v));
}
__device__ __forceinline__ void cpa4(void* dst, const void* src) {
    unsigned sd = (unsigned)__cvta_generic_to_shared(dst);
    asm volatile("cp.async.ca.shared.global [%0], [%1], 4;" :: "r"(sd), "l"(src));
}
#define CP_COMMIT asm volatile("cp.async.commit_group;")
#define CP_WAIT1  asm volatile("cp.async.wait_group 1;")
#define CP_WAIT0  asm volatile("cp.async.wait_group 0;")

// grid-wide barrier: __threadfence (release + L1 IVALL) then counter.
__device__ __forceinline__ void gridbar(unsigned& gen) {
    __threadfence();
    __syncthreads();
    if (threadIdx.x == 0) {
        if (atomicAdd(&g_cnt, 1u) == NBLK - 1) {
            atomicExch(&g_cnt, 0u);
            __threadfence();
            g_gen = gen + 1;
        } else {
            while (g_gen == gen) __nanosleep(32);
        }
    }
    __syncthreads();
    gen++;
}

// ===============================================================
// 64b x 128j GEMM tile, K = NCH*32, cp.async double-buffered, f32x2.
// ===============================================================
#define XS_ST 2176   // 32*68
#define WS_ST 4224   // 32*132
template<bool KMAJOR, int NCH>
__device__ __forceinline__ void gemm_acc(
    const float* __restrict__ Xg, int xstride,
    const float* __restrict__ Wg, size_t wstride, int vw,
    bool wact, ull acc[4][4], float* Xs, float* Ws, int tid)
{
    const int tx = tid & 31, ty = tid >> 5;
    auto stage = [&](int k0, int st) {
#pragma unroll
        for (int i = 0; i < 8; i++) {
            int idx = (i << 8) + tid;
            int k = idx & 31, b = idx >> 5;
            cpa4(&Xs[st * XS_ST + k * 68 + b], Xg + (size_t)b * xstride + k0 + k);
        }
#pragma unroll
        for (int i = 0; i < 16; i++) {
            int idx = (i << 8) + tid;
            int j = KMAJOR ? (idx & 127) : (idx >> 5);
            int k = KMAJOR ? (idx >> 7) : (idx & 31);
            int jc = (j < vw) ? j : 0;
            const float* src = KMAJOR ? (Wg + (size_t)(k0 + k) * wstride + jc)
                                      : (Wg + (size_t)jc * wstride + k0 + k);
            cpa4(&Ws[st * WS_ST + k * 132 + j], src);
        }
        CP_COMMIT;
    };
    stage(0, 0);
    for (int c = 0; c < NCH; c++) {
        int st = c & 1;
        if (c < NCH - 1) { stage((c + 1) << 5, st ^ 1); CP_WAIT1; }
        else            { CP_WAIT0; }
        __syncthreads();
        if (wact) {
#pragma unroll
            for (int kk = 0; kk < 32; kk++) {
                const float4 xa = *(const float4*)(Xs + st * XS_ST + kk * 68 + ty * 8);
                const float4 xb = *(const float4*)(Xs + st * XS_ST + kk * 68 + ty * 8 + 4);
                const float4 wv = *(const float4*)(Ws + st * WS_ST + kk * 132 + tx * 4);
                ull a0 = ((const ull*)&xa)[0], a1 = ((const ull*)&xa)[1];
                ull a2 = ((const ull*)&xb)[0], a3 = ((const ull*)&xb)[1];
                ull w0 = pack2(wv.x, wv.x), w1 = pack2(wv.y, wv.y);
                ull w2 = pack2(wv.z, wv.z), w3 = pack2(wv.w, wv.w);
                fma2(acc[0][0], a0, w0); fma2(acc[0][1], a0, w1);
                fma2(acc[0][2], a0, w2); fma2(acc[0][3], a0, w3);
                fma2(acc[1][0], a1, w0); fma2(acc[1][1], a1, w1);
                fma2(acc[1][2], a1, w2); fma2(acc[1][3], a1, w3);
                fma2(acc[2][0], a2, w0); fma2(acc[2][1], a2, w1);
                fma2(acc[2][2], a2, w2); fma2(acc[2][3], a2, w3);
                fma2(acc[3][0], a3, w0); fma2(acc[3][1], a3, w1);
                fma2(acc[3][2], a3, w2); fma2(acc[3][3], a3, w3);
            }
        }
        __syncthreads();
    }
}

// ---------------------------------------------------------------
__global__ void k_sort(const int* __restrict__ clen, const int* __restrict__ caps,
                       float* __restrict__ out) {
    int i = threadIdx.x;
    __shared__ int len[NB];
    if (i < NB) len[i] = clen[i];
    __syncthreads();
    if (i < NB) {
        int li = len[i], r = 0;
        for (int j = 0; j < NB; j++) {
            int lj = len[j];
            if (lj > li || (lj == li && j < i)) r++;
        }
        g_order[r] = i;
    }
    __syncthreads();
    if (i < NB) {
        int src = g_order[i];
        int dl = len[src] - 1;
        g_declen[i] = dl;
        out[OUT_DECLEN + i] = (float)dl;
        out[OUT_ORDER + i] = (float)src;
        for (int t = 0; t < NL; t++)
            out[OUT_CAPS + i * NL + t] = (float)caps[src * NL + t];
    }
}

// mean (512 blocks) + embeddings (3264 blocks)
__global__ void k_prep(const int* __restrict__ caps, const float* __restrict__ embW,
                       const float* __restrict__ enc) {
    const int bx = blockIdx.x, tid = threadIdx.x;
    if (bx < 512) {
        int b = bx >> 3;
        int e = (bx & 7) * 256 + tid;
        const float* base = enc + (size_t)g_order[b] * NP * NE + e;
        float s = 0.f;
#pragma unroll 7
        for (int p = 0; p < NP; p++) s += base[(size_t)p * NE];
        g_mean[b * NE + e] = s * (1.0f / NP);
    } else {
        int idx = bx - 512;
        int tt = idx >> 6, b = idx & 63;
        int cap = caps[g_order[b] * NL + tt];
        for (int i = tid; i < NEMB; i += 256)
            g_embT[tt][b][i] = embW[(size_t)cap * NEMB + i];
    }
}

// h0/c0: 32-block split-K GEMM, last block combines (self-resetting counter)
__global__ __launch_bounds__(256) void k_init(const float* __restrict__ HW,
                                              const float* __restrict__ CW,
                                              const float* __restrict__ Hb,
                                              const float* __restrict__ Cb) {
    extern __shared__ float dyn[];
    __shared__ int lastf;
    float* Xs = dyn;
    float* Ws = dyn + 2 * XS_ST;
    const int tid = threadIdx.x, tx = tid & 31, ty = tid >> 5;
    const int j0 = (blockIdx.x & 7) * 128, ks = blockIdx.x >> 3;
    const float* W = (j0 < 512) ? (HW + j0) : (CW + j0 - 512);
    ull acc[4][4] = {};
    gemm_acc<true, 16>(g_mean + ks * 512, NE, W + (size_t)ks * 512 * ND, ND, 128,
                       true, acc, Xs, Ws, tid);
#pragma unroll
    for (int p = 0; p < 4; p++) {
        int b0r = ty * 8 + 2 * p;
        float4 lov, hiv;
        unpack2(acc[p][0], lov.x, hiv.x); unpack2(acc[p][1], lov.y, hiv.y);
        unpack2(acc[p][2], lov.z, hiv.z); unpack2(acc[p][3], lov.w, hiv.w);
        *(float4*)&g_initp[ks][b0r * 1024 + j0 + tx * 4] = lov;
        *(float4*)&g_initp[ks][(b0r + 1) * 1024 + j0 + tx * 4] = hiv;
    }
    __threadfence();
    __syncthreads();
    if (tid == 0) lastf = (atomicAdd(&g_icnt, 1u) == 31);
    __syncthreads();
    if (lastf) {
        __threadfence();
        for (int i = tid; i < NB * 1024; i += 256) {
            int b = i >> 10, j = i & 1023;
            float s = g_initp[0][i] + g_initp[1][i] + g_initp[2][i] + g_initp[3][i];
            if (j < 512) g_h[0][b * ND + j] = s + Hb[j];
            else         g_c[b * ND + j - 512] = s + Cb[j - 512];
        }
        if (tid == 0) atomicExch(&g_icnt, 0u);
    }
}

// ---------------------------------------------------------------
// att1 tile (inside persistent kernel): 128m x 128n, K=2048.
// ---------------------------------------------------------------
#define AXS_ST 4224
__device__ void att1_tile(int bn, int bm, const float* __restrict__ enc,
                          const float* __restrict__ W, const float* __restrict__ bias,
                          float* dyn, const int* sO) {
    float* Xs = dyn;
    float* Ws = dyn + 2 * AXS_ST;
    __shared__ int rowBase[128];
    const int tid = threadIdx.x;
    const int row0 = bm * 128;
    __syncthreads();
    if (tid < 128) {
        int m = row0 + tid;
        rowBase[tid] = sO[m / NP] * NP + (m % NP);
    }
    __syncthreads();
    const int tx = tid & 31, ty = tid >> 5;
    ull acc[8][4] = {};
    auto stage = [&](int k0, int st) {
#pragma unroll
        for (int i = 0; i < 16; i++) {
            int idx = (i << 8) + tid;
            int k = idx & 31, m = idx >> 5;
            cpa4(&Xs[st * AXS_ST + k * 132 + m], enc + (size_t)rowBase[m] * NE + k0 + k);
        }
#pragma unroll
        for (int i = 0; i < 16; i++) {
            int idx = (i << 8) + tid;
            int j = idx & 127, k = idx >> 7;
            cpa4(&Ws[st * AXS_ST + k * 132 + j], W + (size_t)(k0 + k) * NA + bn * 128 + j);
        }
        CP_COMMIT;
    };
    stage(0, 0);
    for (int c = 0; c < 64; c++) {
        int st = c & 1;
        if (c < 63) { stage((c + 1) << 5, st ^ 1); CP_WAIT1; }
        else        { CP_WAIT0; }
        __syncthreads();
#pragma unroll
        for (int kk = 0; kk < 32; kk++) {
            const float* xrow = Xs + st * AXS_ST + kk * 132 + ty * 16;
            const float4 x0 = *(const float4*)(xrow);
            const float4 x1 = *(const float4*)(xrow + 4);
            const float4 x2 = *(const float4*)(xrow + 8);
            const float4 x3 = *(const float4*)(xrow + 12);
            const float4 wv = *(const float4*)(Ws + st * AXS_ST + kk * 132 + tx * 4);
            ull a[8];
            a[0] = ((const ull*)&x0)[0]; a[1] = ((const ull*)&x0)[1];
            a[2] = ((const ull*)&x1)[0]; a[3] = ((const ull*)&x1)[1];
            a[4] = ((const ull*)&x2)[0]; a[5] = ((const ull*)&x2)[1];
            a[6] = ((const ull*)&x3)[0]; a[7] = ((const ull*)&x3)[1];
            ull w0 = pack2(wv.x, wv.x), w1 = pack2(wv.y, wv.y);
            ull w2 = pack2(wv.z, wv.z), w3 = pack2(wv.w, wv.w);
#pragma unroll
            for (int p = 0; p < 8; p++) {
                fma2(acc[p][0], a[p], w0); fma2(acc[p][1], a[p], w1);
                fma2(acc[p][2], a[p], w2); fma2(acc[p][3], a[p], w3);
            }
        }
        __syncthreads();
    }
    const float4 bv = *(const float4*)&bias[bn * 128 + tx * 4];
#pragma unroll
    for (int p = 0; p < 8; p++) {
        float4 lov, hiv;
        unpack2(acc[p][0], lov.x, hiv.x); unpack2(acc[p][1], lov.y, hiv.y);
        unpack2(acc[p][2], lov.z, hiv.z); unpack2(acc[p][3], lov.w, hiv.w);
        lov.x += bv.x; lov.y += bv.y; lov.z += bv.z; lov.w += bv.w;
        hiv.x += bv.x; hiv.y += bv.y; hiv.z += bv.z; hiv.w += bv.w;
        size_t m0 = row0 + ty * 16 + 2 * p;
        *(float4*)&g_att1[m0 * NA + bn * 128 + tx * 4] = lov;
        *(float4*)&g_att1[(m0 + 1) * NA + bn * 128 + tx * 4] = hiv;
    }
}

// ---------------------------------------------------------------
// phase1: 131 tiles — att2 [0,4), gate [4,20), gates-emb [20,36),
// gates-h [36,52), fc(t-1) [52,131). t==NT: fc only.
// ---------------------------------------------------------------
__device__ void phase1(int bx, int t,
        const float* __restrict__ attW, const float* __restrict__ attb,
        const float* __restrict__ fbW,  const float* __restrict__ fbb,
        const float* __restrict__ Wih,  const float* __restrict__ Whh,
        const float* __restrict__ bih,  const float* __restrict__ bhh,
        const float* __restrict__ fcW,  const float* __restrict__ fcb,
        float* __restrict__ out, float* dyn, const int* sD) {
    float* Xs = dyn;
    float* Ws = dyn + 2 * XS_ST;
    const int tid = threadIdx.x;
    const int tx = tid & 31, ty = tid >> 5;
    const float* h = g_h[t & 1];
    const int tprev = t - 1;
    ull acc[4][4] = {};

    if (bx < 52) {
        if (t >= NT) return;
        const bool wact = (t < sD[ty * 8]);
        if (bx < 4) {
            int j0 = bx * 128;
            gemm_acc<true, 16>(h, ND, attW + j0, NA, 128, wact, acc, Xs, Ws, tid);
            if (wact) {
                const float4 bv = *(const float4*)&attb[j0 + tx * 4];
#pragma unroll
                for (int p = 0; p < 4; p++) {
                    int b0r = ty * 8 + 2 * p;
                    float4 lov, hiv;
                    unpack2(acc[p][0], lov.x, hiv.x); unpack2(acc[p][1], lov.y, hiv.y);
                    unpack2(acc[p][2], lov.z, hiv.z); unpack2(acc[p][3], lov.w, hiv.w);
                    lov.x += bv.x; lov.y += bv.y; lov.z += bv.z; lov.w += bv.w;
                    hiv.x += bv.x; hiv.y += bv.y; hiv.z += bv.z; hiv.w += bv.w;
                    *(float4*)&g_att2[b0r * NA + j0 + tx * 4] = lov;
                    *(float4*)&g_att2[(b0r + 1) * NA + j0 + tx * 4] = hiv;
                }
            }
        } else if (bx < 20) {
            int jj0 = (bx - 4) * 128;
            gemm_acc<true, 16>(h, ND, fbW + jj0, NE, 128, wact, acc, Xs, Ws, tid);
            if (wact) {
                const float4 bv = *(const float4*)&fbb[jj0 + tx * 4];
#pragma unroll
                for (int p = 0; p < 4; p++) {
                    int b0r = ty * 8 + 2 * p;
                    float4 lov, hiv;
                    unpack2(acc[p][0], lov.x, hiv.x); unpack2(acc[p][1], lov.y, hiv.y);
                    unpack2(acc[p][2], lov.z, hiv.z); unpack2(acc[p][3], lov.w, hiv.w);
                    lov.x = sigf(lov.x + bv.x); lov.y = sigf(lov.y + bv.y);
                    lov.z = sigf(lov.z + bv.z); lov.w = sigf(lov.w + bv.w);
                    hiv.x = sigf(hiv.x + bv.x); hiv.y = sigf(hiv.y + bv.y);
                    hiv.z = sigf(hiv.z + bv.z); hiv.w = sigf(hiv.w + bv.w);
                    *(float4*)&g_gate[b0r * NE + jj0 + tx * 4] = lov;
                    *(float4*)&g_gate[(b0r + 1) * NE + jj0 + tx * 4] = hiv;
                }
            }
        } else if (bx < 36) {
            int j0 = (bx - 20) * 128;
            gemm_acc<false, 16>(&g_embT[t][0][0], NEMB, Wih + (size_t)j0 * NX, NX, 128,
                                wact, acc, Xs, Ws, tid);
            if (wact) {
                const float4 b1 = *(const float4*)&bih[j0 + tx * 4];
                const float4 b2 = *(const float4*)&bhh[j0 + tx * 4];
#pragma unroll
                for (int p = 0; p < 4; p++) {
                    int b0r = ty * 8 + 2 * p;
                    float4 lov, hiv;
                    unpack2(acc[p][0], lov.x, hiv.x); unpack2(acc[p][1], lov.y, hiv.y);
                    unpack2(acc[p][2], lov.z, hiv.z); unpack2(acc[p][3], lov.w, hiv.w);
                    lov.x += b1.x + b2.x; lov.y += b1.y + b2.y;
                    lov.z += b1.z + b2.z; lov.w += b1.w + b2.w;
                    hiv.x += b1.x + b2.x; hiv.y += b1.y + b2.y;
                    hiv.z += b1.z + b2.z; hiv.w += b1.w + b2.w;
                    *(float4*)&g_gxh_e[b0r * (4 * ND) + j0 + tx * 4] = lov;
                    *(float4*)&g_gxh_e[(b0r + 1) * (4 * ND) + j0 + tx * 4] = hiv;
                }
            }
        } else {
            int j0 = (bx - 36) * 128;
            gemm_acc<false, 16>(h, ND, Whh + (size_t)j0 * ND, ND, 128,
                                wact, acc, Xs, Ws, tid);
            if (wact) {
#pragma unroll
                for (int p = 0; p < 4; p++) {
                    int b0r = ty * 8 + 2 * p;
                    float4 lov, hiv;
                    unpack2(acc[p][0], lov.x, hiv.x); unpack2(acc[p][1], lov.y, hiv.y);
                    unpack2(acc[p][2], lov.z, hiv.z); unpack2(acc[p][3], lov.w, hiv.w);
                    *(float4*)&g_gxh_h[b0r * (4 * ND) + j0 + tx * 4] = lov;
                    *(float4*)&g_gxh_h[(b0r + 1) * (4 * ND) + j0 + tx * 4] = hiv;
                }
            }
        }
    } else {
        if (tprev < 0) return;
        const bool wact = (tprev < sD[ty * 8]);
        int j0 = (bx - 52) * 128;
        int vw = NV - j0; if (vw > 128) vw = 128;
        gemm_acc<true, 16>(h, ND, fcW + j0, NV, vw, wact, acc, Xs, Ws, tid);
        const bool vec = (j0 + 128 <= NV);
#pragma unroll
        for (int p = 0; p < 4; p++) {
            int bA = ty * 8 + 2 * p, bB = bA + 1;
            bool actA = tprev < sD[bA];
            bool actB = tprev < sD[bB];
            if (vec) {
                const float4 bv = *(const float4*)&fcb[j0 + tx * 4];
                float4 lov, hiv;
                unpack2(acc[p][0], lov.x, hiv.x); unpack2(acc[p][1], lov.y, hiv.y);
                unpack2(acc[p][2], lov.z, hiv.z); unpack2(acc[p][3], lov.w, hiv.w);
                lov.x = actA ? lov.x + bv.x : 0.f; lov.y = actA ? lov.y + bv.y : 0.f;
                lov.z = actA ? lov.z + bv.z : 0.f; lov.w = actA ? lov.w + bv.w : 0.f;
                hiv.x = actB ? hiv.x + bv.x : 0.f; hiv.y = actB ? hiv.y + bv.y : 0.f;
                hiv.z = actB ? hiv.z + bv.z : 0.f; hiv.w = actB ? hiv.w + bv.w : 0.f;
                *(float4*)&out[OUT_PRED + (size_t)(bA * NT + tprev) * NV + j0 + tx * 4] = lov;
                *(float4*)&out[OUT_PRED + (size_t)(bB * NT + tprev) * NV + j0 + tx * 4] = hiv;
            } else {
#pragma unroll
                for (int jj = 0; jj < 4; jj++) {
                    int v = j0 + tx * 4 + jj;
                    if (v < NV) {
                        float lo, hi; unpack2(acc[p][jj], lo, hi);
                        float bvv = fcb[v];
                        out[OUT_PRED + (size_t)(bA * NT + tprev) * NV + v] = actA ? lo + bvv : 0.f;
                        out[OUT_PRED + (size_t)(bB * NT + tprev) * NV + v] = actB ? hi + bvv : 0.f;
                    }
                }
            }
        }
    }
}

// ---------------------------------------------------------------
// phase2: 128 tiles (b, half). alpha (redundant per half) + awe e-slice.
// ---------------------------------------------------------------
__device__ void phase2(int tile, int t, const float* __restrict__ fullw,
                       const float* __restrict__ fullb, const float* __restrict__ enc,
                       float* __restrict__ out, const int* sD, const int* sO) {
    __shared__ float att2s[NA];
    __shared__ float ws[NA];
    __shared__ float ev[NP];
    __shared__ float al[NP + 4];
    __shared__ float red[8];
    __shared__ float smax, ssum;
    const int b = tile >> 1, half = tile & 1;
    const int tid = threadIdx.x, warp = tid >> 5, lane = tid & 31;
    float* aout = out + OUT_ALPHA + ((size_t)b * NT + t) * NP;
    if (t >= sD[b]) {
        if (half == 0)
            for (int p = tid; p < NP; p += 256) aout[p] = 0.f;
        return;
    }
    for (int i = tid; i < NA; i += 256) { att2s[i] = g_att2[b * NA + i]; ws[i] = fullw[i]; }
    __syncthreads();
    const float fb = fullb[0];
    for (int p = warp; p < NP; p += 8) {
        const float* a1 = g_att1 + ((size_t)(b * NP + p)) * NA;
        float s = 0.f;
#pragma unroll 4
        for (int a = lane; a < NA; a += 32) {
            float v = a1[a] + att2s[a];
            s += fmaxf(v, 0.f) * ws[a];
        }
#pragma unroll
        for (int o = 16; o; o >>= 1) s += __shfl_xor_sync(0xffffffffu, s, o);
        if (lane == 0) ev[p] = s + fb;
    }
    __syncthreads();
    float v = (tid < NP) ? ev[tid] : -3.0e38f;
    float m = v;
#pragma unroll
    for (int o = 16; o; o >>= 1) m = fmaxf(m, __shfl_xor_sync(0xffffffffu, m, o));
    if (lane == 0) red[warp] = m;
    __syncthreads();
    if (tid == 0) { float mm = red[0]; for (int i = 1; i < 8; i++) mm = fmaxf(mm, red[i]); smax = mm; }
    __syncthreads();
    float ex = (tid < NP) ? expf(v - smax) : 0.f;
    float s2 = ex;
#pragma unroll
    for (int o = 16; o; o >>= 1) s2 += __shfl_xor_sync(0xffffffffu, s2, o);
    if (lane == 0) red[warp] = s2;
    __syncthreads();
    if (tid == 0) { float ss = 0.f; for (int i = 0; i < 8; i++) ss += red[i]; ssum = ss; }
    __syncthreads();
    if (tid < NP) {
        float a = ex / ssum;
        al[tid] = a;
        if (half == 0) aout[tid] = a;
    }
    if (tid >= NP && tid < NP + 4) al[tid] = 0.f;
    __syncthreads();
    // awe for this half's 1024-wide e slice (4 e per thread)
    const int e0 = half * 1024 + tid * 4;
    const float* eb = enc + (size_t)sO[b] * NP * NE + e0;
    float4 aw = {0.f, 0.f, 0.f, 0.f};
    for (int p = 0; p < NP; p += 2) {
        float a0 = al[p], a1 = al[p + 1];
        const float4 r0 = *(const float4*)(eb + (size_t)p * NE);
        const float4 r1 = *(const float4*)(eb + (size_t)(p + 1) * NE);
        aw.x += a0 * r0.x + a1 * r1.x; aw.y += a0 * r0.y + a1 * r1.y;
        aw.z += a0 * r0.z + a1 * r1.z; aw.w += a0 * r0.w + a1 * r1.w;
    }
    const float4 g = *(const float4*)&g_gate[b * NE + e0];
    float4 o0 = {aw.x * g.x, aw.y * g.y, aw.z * g.z, aw.w * g.w};
    *(float4*)&g_awe[b * NE + e0] = o0;
}

// ---------------------------------------------------------------
// phase3: 128 tiles — gawe j-tile x 8-way K-split (K=256 each)
// ---------------------------------------------------------------
__device__ void phase3(int tile, int t, const float* __restrict__ Wih,
                       float* dyn, const int* sD) {
    float* Xs = dyn;
    float* Ws = dyn + 2 * XS_ST;
    const int tid = threadIdx.x;
    const int tx = tid & 31, ty = tid >> 5;
    const int j0 = (tile & 15) * 128;
    const int ks = tile >> 4;
    const bool wact = (t < sD[ty * 8]);
    ull acc[4][4] = {};
    gemm_acc<false, 8>(g_awe + ks * 256, NE, Wih + (size_t)j0 * NX + 512 + ks * 256, NX, 128,
                       wact, acc, Xs, Ws, tid);
    if (wact) {
#pragma unroll
        for (int p = 0; p < 4; p++) {
            int b0r = ty * 8 + 2 * p;
            float4 lov, hiv;
            unpack2(acc[p][0], lov.x, hiv.x); unpack2(acc[p][1], lov.y, hiv.y);
            unpack2(acc[p][2], lov.z, hiv.z); unpack2(acc[p][3], lov.w, hiv.w);
            *(float4*)&g_gawe[ks][b0r * (4 * ND) + j0 + tx * 4] = lov;
            *(float4*)&g_gawe[ks][(b0r + 1) * (4 * ND) + j0 + tx * 4] = hiv;
        }
    }
}

// phase4: lstm pointwise (tile = b)
__device__ void phase4(int b, int t, const int* sD) {
    if (t >= sD[b]) return;
    const int tid = threadIdx.x;
    for (int d = tid; d < ND; d += 256) {
        float gv[4];
#pragma unroll
        for (int q = 0; q < 4; q++) {
            int j = q * ND + d;
            float s = g_gxh_e[b * (4 * ND) + j] + g_gxh_h[b * (4 * ND) + j];
#pragma unroll
            for (int ks = 0; ks < 8; ks++) s += g_gawe[ks][b * (4 * ND) + j];
            gv[q] = s;
        }
        float i_ = sigf(gv[0]);
        float f_ = sigf(gv[1]);
        float gg = tanhf(gv[2]);
        float o_ = sigf(gv[3]);
        float c = f_ * g_c[b * ND + d] + i_ * gg;
        g_c[b * ND + d] = c;
        g_h[(t & 1) ^ 1][b * ND + d] = o_ * tanhf(c);
    }
}

// ---------------------------------------------------------------
// Persistent kernel: att1 prologue + 51-step loop with grid barriers.
// ---------------------------------------------------------------
__global__ __launch_bounds__(256) void k_loop(
        const float* __restrict__ enc,
        const float* __restrict__ attEncW, const float* __restrict__ attEncB,
        const float* __restrict__ attW, const float* __restrict__ attb,
        const float* __restrict__ fbW,  const float* __restrict__ fbb,
        const float* __restrict__ fullw, const float* __restrict__ fullb,
        const float* __restrict__ Wih,  const float* __restrict__ Whh,
        const float* __restrict__ bih,  const float* __restrict__ bhh,
        const float* __restrict__ fcW,  const float* __restrict__ fcb,
        float* __restrict__ out) {
    extern __shared__ float dyn[];
    __shared__ int sD[NB], sO[NB];
    const int bid = blockIdx.x, tid = threadIdx.x;
    unsigned gen = g_gen;          // read BEFORE any barrier arrival
    if (tid < NB) { sD[tid] = g_declen[tid]; sO[tid] = g_order[tid]; }
    __syncthreads();

    // ---- att1 prologue (392 tiles) ----
    for (int tile = bid; tile < 4 * 98; tile += NBLK)
        att1_tile(tile & 3, tile >> 2, enc, attEncW, attEncB, dyn, sO);
    gridbar(gen);

    // ---- step loop ----
    for (int t = 0; t <= NT; t++) {
        if (bid < 131) phase1(bid, t, attW, attb, fbW, fbb, Wih, Whh,
                              bih, bhh, fcW, fcb, out, dyn, sD);
        if (t == NT) break;
        gridbar(gen);
        if (bid < 2 * NB) phase2(bid, t, fullw, fullb, enc, out, sD, sO);
        gridbar(gen);
        if (bid < 128) phase3(bid, t, Wih, dyn, sD);
        gridbar(gen);
        if (bid < NB) phase4(bid, t, sD);
        gridbar(gen);
    }
}

// ---------------------------------------------------------------
extern "C" void kernel_launch(void* const* d_in, const int* in_sizes, int n_in,
                              void* d_out, int out_size) {
    (void)in_sizes; (void)n_in; (void)out_size;
    const float* enc     = (const float*)d_in[0];
    const int*   caps    = (const int*)d_in[1];
    const int*   clen    = (const int*)d_in[2];
    const float* embW    = (const float*)d_in[3];
    const float* attEncW = (const float*)d_in[4];
    const float* attEncB = (const float*)d_in[5];
    const float* attDecW = (const float*)d_in[6];
    const float* attDecB = (const float*)d_in[7];
    const float* fullW   = (const float*)d_in[8];
    const float* fullB   = (const float*)d_in[9];
    const float* Wih     = (const float*)d_in[10];
    const float* Whh     = (const float*)d_in[11];
    const float* bih     = (const float*)d_in[12];
    const float* bhh     = (const float*)d_in[13];
    const float* iHW     = (const float*)d_in[14];
    const float* iHb     = (const float*)d_in[15];
    const float* iCW     = (const float*)d_in[16];
    const float* iCb     = (const float*)d_in[17];
    const float* fbW     = (const float*)d_in[18];
    const float* fbb     = (const float*)d_in[19];
    const float* fcW     = (const float*)d_in[20];
    const float* fcb     = (const float*)d_in[21];
    float* out = (float*)d_out;

    const int SM_STEP = (2 * XS_ST + 2 * WS_ST) * 4;   // 51200
    const int SM_LOOP = (4 * AXS_ST) * 4;              // 67584
    static int configured = 0;
    if (!configured) {
        cudaFuncSetAttribute(k_init, cudaFuncAttributeMaxDynamicSharedMemorySize, SM_STEP);
        cudaFuncSetAttribute(k_loop, cudaFuncAttributeMaxDynamicSharedMemorySize, SM_LOOP);
        configured = 1;
    }

    k_sort<<<1, 64>>>(clen, caps, out);
    k_prep<<<512 + NT * NB, 256>>>(caps, embW, enc);
    k_init<<<32, 256, SM_STEP>>>(iHW, iCW, iHb, iCb);
    k_loop<<<NBLK, 256, SM_LOOP>>>(enc, attEncW, attEncB, attDecW, attDecB,
                                   fbW, fbb, fullW, fullB, Wih, Whh,
                                   bih, bhh, fcW, fcb, out);
}

// round 9
// speedup vs baseline: 2.7575x; 1.1895x over previous
#include <cuda_runtime.h>
#include <math.h>

#define NB 64
#define NP 196
#define NE 2048
#define ND 512
#define NA 512
#define NEMB 512
#define NV 10000
#define NL 52
#define NT 51
#define NX 2560
#define NBLK 148

#define OUT_PRED   0
#define OUT_CAPS   32640000
#define OUT_DECLEN 32643328
#define OUT_ALPHA  32643392
#define OUT_ORDER  33283136

typedef unsigned long long ull;

// ---- scratch ----
__device__ int   g_order[NB];
__device__ int   g_declen[NB];
__device__ float g_att1[(size_t)NB * NP * NA];
__device__ float g_h[2][NB * ND];
__device__ float g_c[NB * ND];
__device__ float g_att2[NB * NA];
__device__ float g_gate[NB * NE];
__device__ float g_awe[NB * NE];
__device__ float g_embT[NT][NB][NEMB];
__device__ float g_embg[NT][NB * 4 * ND];     // precomputed emb@Wih^T + biases
__device__ float g_gxh_h[NB * 4 * ND];
__device__ float g_gawe[4][NB * 4 * ND];
__device__ float g_mean[NB * NE];
__device__ float g_initp[4][NB * 1024];

// ---- barrier state ----
__device__ unsigned g_cnt;
__device__ volatile unsigned g_gen;
__device__ unsigned g_icnt;

__device__ __forceinline__ float sigf(float x) { return 1.f / (1.f + expf(-x)); }

__device__ __forceinline__ ull pack2(float x, float y) {
    ull d; asm("mov.b64 %0, {%1, %2};" : "=l"(d) : "f"(x), "f"(y)); return d;
}
__device__ __forceinline__ void fma2(ull& d, ull a, ull b) {
    asm("fma.rn.f32x2 %0, %1, %2, %0;" : "+l"(d) : "l"(a), "l"(b));
}
__device__ __forceinline__ void unpack2(ull v, float& lo, float& hi) {
    asm("mov.b64 {%0, %1}, %2;" : "=f"(lo), "=f"(hi) : "l"(v));
}
__device__ __forceinline__ void cpa4(void* dst, const void* src) {
    unsigned sd = (unsigned)__cvta_generic_to_shared(dst);
    asm volatile("cp.async.ca.shared.global [%0], [%1], 4;" :: "r"(sd), "l"(src));
}
#define CP_COMMIT asm volatile("cp.async.commit_group;")
#define CP_WAIT1  asm volatile("cp.async.wait_group 1;")
#define CP_WAIT0  asm volatile("cp.async.wait_group 0;")

__device__ __forceinline__ void gridbar(unsigned& gen) {
    __threadfence();
    __syncthreads();
    if (threadIdx.x == 0) {
        if (atomicAdd(&g_cnt, 1u) == NBLK - 1) {
            atomicExch(&g_cnt, 0u);
            __threadfence();
            g_gen = gen + 1;
        } else {
            while (g_gen == gen) __nanosleep(32);
        }
    }
    __syncthreads();
    gen++;
}

// ===============================================================
// 256-thread 64b x 128j GEMM (used by init / embg / att1-helper kernels)
// ===============================================================
#define XS_ST 2176
#define WS_ST 4224
template<bool KMAJOR, int NCH>
__device__ __forceinline__ void gemm_acc(
    const float* __restrict__ Xg, int xstride,
    const float* __restrict__ Wg, size_t wstride, int vw,
    bool wact, ull acc[4][4], float* Xs, float* Ws, int tid)
{
    const int tx = tid & 31, ty = tid >> 5;
    auto stage = [&](int k0, int st) {
#pragma unroll
        for (int i = 0; i < 8; i++) {
            int idx = (i << 8) + tid;
            int k = idx & 31, b = idx >> 5;
            cpa4(&Xs[st * XS_ST + k * 68 + b], Xg + (size_t)b * xstride + k0 + k);
        }
#pragma unroll
        for (int i = 0; i < 16; i++) {
            int idx = (i << 8) + tid;
            int j = KMAJOR ? (idx & 127) : (idx >> 5);
            int k = KMAJOR ? (idx >> 7) : (idx & 31);
            int jc = (j < vw) ? j : 0;
            const float* src = KMAJOR ? (Wg + (size_t)(k0 + k) * wstride + jc)
                                      : (Wg + (size_t)jc * wstride + k0 + k);
            cpa4(&Ws[st * WS_ST + k * 132 + j], src);
        }
        CP_COMMIT;
    };
    stage(0, 0);
    for (int c = 0; c < NCH; c++) {
        int st = c & 1;
        if (c < NCH - 1) { stage((c + 1) << 5, st ^ 1); CP_WAIT1; }
        else            { CP_WAIT0; }
        __syncthreads();
        if (wact) {
#pragma unroll
            for (int kk = 0; kk < 32; kk++) {
                const float4 xa = *(const float4*)(Xs + st * XS_ST + kk * 68 + ty * 8);
                const float4 xb = *(const float4*)(Xs + st * XS_ST + kk * 68 + ty * 8 + 4);
                const float4 wv = *(const float4*)(Ws + st * WS_ST + kk * 132 + tx * 4);
                ull a0 = ((const ull*)&xa)[0], a1 = ((const ull*)&xa)[1];
                ull a2 = ((const ull*)&xb)[0], a3 = ((const ull*)&xb)[1];
                ull w0 = pack2(wv.x, wv.x), w1 = pack2(wv.y, wv.y);
                ull w2 = pack2(wv.z, wv.z), w3 = pack2(wv.w, wv.w);
                fma2(acc[0][0], a0, w0); fma2(acc[0][1], a0, w1);
                fma2(acc[0][2], a0, w2); fma2(acc[0][3], a0, w3);
                fma2(acc[1][0], a1, w0); fma2(acc[1][1], a1, w1);
                fma2(acc[1][2], a1, w2); fma2(acc[1][3], a1, w3);
                fma2(acc[2][0], a2, w0); fma2(acc[2][1], a2, w1);
                fma2(acc[2][2], a2, w2); fma2(acc[2][3], a2, w3);
                fma2(acc[3][0], a3, w0); fma2(acc[3][1], a3, w1);
                fma2(acc[3][2], a3, w2); fma2(acc[3][3], a3, w3);
            }
        }
        __syncthreads();
    }
}

// ===============================================================
// 512-thread 64b x 64j GEMM (persistent loop). Thread: 8 rows x 1 col.
// tx = tid&63 (col), ty = tid>>6 (row group). Per kk: 2 bcast LDS.128 +
// 1 LDS.32 + 8 fma2.
// ===============================================================
#define X64 2176   // 32*68
#define W64 2176
template<bool KMAJOR, int NCH>
__device__ __forceinline__ void gemm64(
    const float* __restrict__ Xg, int xstride,
    const float* __restrict__ Wg, size_t wstride, int vw,
    bool wact, ull acc[4], float* Xs, float* Ws, int tid)
{
    const int tx = tid & 63, ty = tid >> 6;
    auto stage = [&](int k0, int st) {
#pragma unroll
        for (int i = 0; i < 4; i++) {
            int idx = (i << 9) + tid;
            int k = idx & 31, b = idx >> 5;
            cpa4(&Xs[st * X64 + k * 68 + b], Xg + (size_t)b * xstride + k0 + k);
        }
#pragma unroll
        for (int i = 0; i < 4; i++) {
            int idx = (i << 9) + tid;
            int j = KMAJOR ? (idx & 63) : (idx >> 5);
            int k = KMAJOR ? (idx >> 6) : (idx & 31);
            int jc = (j < vw) ? j : 0;
            const float* src = KMAJOR ? (Wg + (size_t)(k0 + k) * wstride + jc)
                                      : (Wg + (size_t)jc * wstride + k0 + k);
            cpa4(&Ws[st * W64 + k * 68 + j], src);
        }
        CP_COMMIT;
    };
    stage(0, 0);
    for (int c = 0; c < NCH; c++) {
        int st = c & 1;
        if (c < NCH - 1) { stage((c + 1) << 5, st ^ 1); CP_WAIT1; }
        else            { CP_WAIT0; }
        __syncthreads();
        if (wact) {
#pragma unroll
            for (int kk = 0; kk < 32; kk++) {
                const float4 xa = *(const float4*)(Xs + st * X64 + kk * 68 + ty * 8);
                const float4 xb = *(const float4*)(Xs + st * X64 + kk * 68 + ty * 8 + 4);
                float w = Ws[st * W64 + kk * 68 + tx];
                ull wv = pack2(w, w);
                fma2(acc[0], ((const ull*)&xa)[0], wv);
                fma2(acc[1], ((const ull*)&xa)[1], wv);
                fma2(acc[2], ((const ull*)&xb)[0], wv);
                fma2(acc[3], ((const ull*)&xb)[1], wv);
            }
        }
        __syncthreads();
    }
}

// ---------------------------------------------------------------
__global__ void k_sort(const int* __restrict__ clen, const int* __restrict__ caps,
                       float* __restrict__ out) {
    int i = threadIdx.x;
    __shared__ int len[NB];
    if (i < NB) len[i] = clen[i];
    __syncthreads();
    if (i < NB) {
        int li = len[i], r = 0;
        for (int j = 0; j < NB; j++) {
            int lj = len[j];
            if (lj > li || (lj == li && j < i)) r++;
        }
        g_order[r] = i;
    }
    __syncthreads();
    if (i < NB) {
        int src = g_order[i];
        int dl = len[src] - 1;
        g_declen[i] = dl;
        out[OUT_DECLEN + i] = (float)dl;
        out[OUT_ORDER + i] = (float)src;
        for (int t = 0; t < NL; t++)
            out[OUT_CAPS + i * NL + t] = (float)caps[src * NL + t];
    }
}

__global__ void k_prep(const int* __restrict__ caps, const float* __restrict__ embW,
                       const float* __restrict__ enc) {
    const int bx = blockIdx.x, tid = threadIdx.x;
    if (bx < 512) {
        int b = bx >> 3;
        int e = (bx & 7) * 256 + tid;
        const float* base = enc + (size_t)g_order[b] * NP * NE + e;
        float s = 0.f;
#pragma unroll 7
        for (int p = 0; p < NP; p++) s += base[(size_t)p * NE];
        g_mean[b * NE + e] = s * (1.0f / NP);
    } else {
        int idx = bx - 512;
        int tt = idx >> 6, b = idx & 63;
        int cap = caps[g_order[b] * NL + tt];
        for (int i = tid; i < NEMB; i += 256)
            g_embT[tt][b][i] = embW[(size_t)cap * NEMB + i];
    }
}

// emb-gates for ALL steps: grid 51*16
__global__ __launch_bounds__(256) void k_embg(const float* __restrict__ Wih,
                                              const float* __restrict__ bih,
                                              const float* __restrict__ bhh) {
    extern __shared__ float dyn[];
    float* Xs = dyn;
    float* Ws = dyn + 2 * XS_ST;
    const int tid = threadIdx.x, tx = tid & 31, ty = tid >> 5;
    const int t = blockIdx.x >> 4;
    const int j0 = (blockIdx.x & 15) * 128;
    ull acc[4][4] = {};
    gemm_acc<false, 16>(&g_embT[t][0][0], NEMB, Wih + (size_t)j0 * NX, NX, 128,
                        true, acc, Xs, Ws, tid);
#pragma unroll
    for (int p = 0; p < 4; p++) {
        int b0r = ty * 8 + 2 * p;
        const float4 b1 = *(const float4*)&bih[j0 + tx * 4];
        const float4 b2 = *(const float4*)&bhh[j0 + tx * 4];
        float4 lov, hiv;
        unpack2(acc[p][0], lov.x, hiv.x); unpack2(acc[p][1], lov.y, hiv.y);
        unpack2(acc[p][2], lov.z, hiv.z); unpack2(acc[p][3], lov.w, hiv.w);
        lov.x += b1.x + b2.x; lov.y += b1.y + b2.y; lov.z += b1.z + b2.z; lov.w += b1.w + b2.w;
        hiv.x += b1.x + b2.x; hiv.y += b1.y + b2.y; hiv.z += b1.z + b2.z; hiv.w += b1.w + b2.w;
        *(float4*)&g_embg[t][b0r * (4 * ND) + j0 + tx * 4] = lov;
        *(float4*)&g_embg[t][(b0r + 1) * (4 * ND) + j0 + tx * 4] = hiv;
    }
}

// h0/c0 split-K GEMM + combine
__global__ __launch_bounds__(256) void k_init(const float* __restrict__ HW,
                                              const float* __restrict__ CW,
                                              const float* __restrict__ Hb,
                                              const float* __restrict__ Cb) {
    extern __shared__ float dyn[];
    __shared__ int lastf;
    float* Xs = dyn;
    float* Ws = dyn + 2 * XS_ST;
    const int tid = threadIdx.x, tx = tid & 31, ty = tid >> 5;
    const int j0 = (blockIdx.x & 7) * 128, ks = blockIdx.x >> 3;
    const float* W = (j0 < 512) ? (HW + j0) : (CW + j0 - 512);
    ull acc[4][4] = {};
    gemm_acc<true, 16>(g_mean + ks * 512, NE, W + (size_t)ks * 512 * ND, ND, 128,
                       true, acc, Xs, Ws, tid);
#pragma unroll
    for (int p = 0; p < 4; p++) {
        int b0r = ty * 8 + 2 * p;
        float4 lov, hiv;
        unpack2(acc[p][0], lov.x, hiv.x); unpack2(acc[p][1], lov.y, hiv.y);
        unpack2(acc[p][2], lov.z, hiv.z); unpack2(acc[p][3], lov.w, hiv.w);
        *(float4*)&g_initp[ks][b0r * 1024 + j0 + tx * 4] = lov;
        *(float4*)&g_initp[ks][(b0r + 1) * 1024 + j0 + tx * 4] = hiv;
    }
    __threadfence();
    __syncthreads();
    if (tid == 0) lastf = (atomicAdd(&g_icnt, 1u) == 31);
    __syncthreads();
    if (lastf) {
        __threadfence();
        for (int i = tid; i < NB * 1024; i += 256) {
            int b = i >> 10, j = i & 1023;
            float s = g_initp[0][i] + g_initp[1][i] + g_initp[2][i] + g_initp[3][i];
            if (j < 512) g_h[0][b * ND + j] = s + Hb[j];
            else         g_c[b * ND + j - 512] = s + Cb[j - 512];
        }
        if (tid == 0) atomicExch(&g_icnt, 0u);
    }
}

// att1 standalone: 128m x 128n, K=2048, grid (4,98)
#define AXS_ST 4224
__global__ __launch_bounds__(256) void k_att1(const float* __restrict__ enc,
                                              const float* __restrict__ W,
                                              const float* __restrict__ bias) {
    extern __shared__ float dyn[];
    float* Xs = dyn;
    float* Ws = dyn + 2 * AXS_ST;
    __shared__ int rowBase[128];
    const int bn = blockIdx.x, bm = blockIdx.y, tid = threadIdx.x;
    const int row0 = bm * 128;
    if (tid < 128) {
        int m = row0 + tid;
        rowBase[tid] = g_order[m / NP] * NP + (m % NP);
    }
    __syncthreads();
    const int tx = tid & 31, ty = tid >> 5;
    ull acc[8][4] = {};
    auto stage = [&](int k0, int st) {
#pragma unroll
        for (int i = 0; i < 16; i++) {
            int idx = (i << 8) + tid;
            int k = idx & 31, m = idx >> 5;
            cpa4(&Xs[st * AXS_ST + k * 132 + m], enc + (size_t)rowBase[m] * NE + k0 + k);
        }
#pragma unroll
        for (int i = 0; i < 16; i++) {
            int idx = (i << 8) + tid;
            int j = idx & 127, k = idx >> 7;
            cpa4(&Ws[st * AXS_ST + k * 132 + j], W + (size_t)(k0 + k) * NA + bn * 128 + j);
        }
        CP_COMMIT;
    };
    stage(0, 0);
    for (int c = 0; c < 64; c++) {
        int st = c & 1;
        if (c < 63) { stage((c + 1) << 5, st ^ 1); CP_WAIT1; }
        else        { CP_WAIT0; }
        __syncthreads();
#pragma unroll
        for (int kk = 0; kk < 32; kk++) {
            const float* xrow = Xs + st * AXS_ST + kk * 132 + ty * 16;
            const float4 x0 = *(const float4*)(xrow);
            const float4 x1 = *(const float4*)(xrow + 4);
            const float4 x2 = *(const float4*)(xrow + 8);
            const float4 x3 = *(const float4*)(xrow + 12);
            const float4 wv = *(const float4*)(Ws + st * AXS_ST + kk * 132 + tx * 4);
            ull a[8];
            a[0] = ((const ull*)&x0)[0]; a[1] = ((const ull*)&x0)[1];
            a[2] = ((const ull*)&x1)[0]; a[3] = ((const ull*)&x1)[1];
            a[4] = ((const ull*)&x2)[0]; a[5] = ((const ull*)&x2)[1];
            a[6] = ((const ull*)&x3)[0]; a[7] = ((const ull*)&x3)[1];
            ull w0 = pack2(wv.x, wv.x), w1 = pack2(wv.y, wv.y);
            ull w2 = pack2(wv.z, wv.z), w3 = pack2(wv.w, wv.w);
#pragma unroll
            for (int p = 0; p < 8; p++) {
                fma2(acc[p][0], a[p], w0); fma2(acc[p][1], a[p], w1);
                fma2(acc[p][2], a[p], w2); fma2(acc[p][3], a[p], w3);
            }
        }
        __syncthreads();
    }
    const float4 bv = *(const float4*)&bias[bn * 128 + tx * 4];
#pragma unroll
    for (int p = 0; p < 8; p++) {
        float4 lov, hiv;
        unpack2(acc[p][0], lov.x, hiv.x); unpack2(acc[p][1], lov.y, hiv.y);
        unpack2(acc[p][2], lov.z, hiv.z); unpack2(acc[p][3], lov.w, hiv.w);
        lov.x += bv.x; lov.y += bv.y; lov.z += bv.z; lov.w += bv.w;
        hiv.x += bv.x; hiv.y += bv.y; hiv.z += bv.z; hiv.w += bv.w;
        size_t m0 = row0 + ty * 16 + 2 * p;
        *(float4*)&g_att1[m0 * NA + bn * 128 + tx * 4] = lov;
        *(float4*)&g_att1[(m0 + 1) * NA + bn * 128 + tx * 4] = hiv;
    }
}

// ---------------------------------------------------------------
// fc tile (64j) for step tprev — writes preds with row masking
// ---------------------------------------------------------------
__device__ void fc_tile(int tile, int tprev, const float* __restrict__ h,
                        const float* __restrict__ fcW, const float* __restrict__ fcb,
                        float* __restrict__ out, float* Xs, float* Ws,
                        const int* sD, int tid) {
    const int tx = tid & 63, ty = tid >> 6;
    int j0 = tile * 64;
    int vw = NV - j0; if (vw > 64) vw = 64;
    const bool wact = (tprev < sD[ty * 8]);
    ull acc[4] = {};
    gemm64<true, 16>(h, ND, fcW + j0, NV, vw, wact, acc, Xs, Ws, tid);
    int col = j0 + tx;
    if (col < NV) {
        float bv = fcb[col];
#pragma unroll
        for (int p = 0; p < 4; p++) {
            int bA = ty * 8 + 2 * p, bB = bA + 1;
            float lo, hi; unpack2(acc[p], lo, hi);
            out[OUT_PRED + (size_t)(bA * NT + tprev) * NV + col] =
                (tprev < sD[bA]) ? lo + bv : 0.f;
            out[OUT_PRED + (size_t)(bB * NT + tprev) * NV + col] =
                (tprev < sD[bB]) ? hi + bv : 0.f;
        }
    }
}

// P1 tile: 0-7 att2, 8-39 gate, 40-71 gates-h
__device__ void p1_tile(int bx, int t,
        const float* __restrict__ attW, const float* __restrict__ attb,
        const float* __restrict__ fbW,  const float* __restrict__ fbb,
        const float* __restrict__ Whh,
        float* Xs, float* Ws, const int* sD, int tid) {
    const int tx = tid & 63, ty = tid >> 6;
    const float* h = g_h[t & 1];
    const bool wact = (t < sD[ty * 8]);
    ull acc[4] = {};
    if (bx < 8) {
        int j0 = bx * 64;
        gemm64<true, 16>(h, ND, attW + j0, NA, 64, wact, acc, Xs, Ws, tid);
        if (wact) {
            float bv = attb[j0 + tx];
#pragma unroll
            for (int p = 0; p < 4; p++) {
                int b0r = ty * 8 + 2 * p;
                float lo, hi; unpack2(acc[p], lo, hi);
                g_att2[b0r * NA + j0 + tx] = lo + bv;
                g_att2[(b0r + 1) * NA + j0 + tx] = hi + bv;
            }
        }
    } else if (bx < 40) {
        int jj0 = (bx - 8) * 64;
        gemm64<true, 16>(h, ND, fbW + jj0, NE, 64, wact, acc, Xs, Ws, tid);
        if (wact) {
            float bv = fbb[jj0 + tx];
#pragma unroll
            for (int p = 0; p < 4; p++) {
                int b0r = ty * 8 + 2 * p;
                float lo, hi; unpack2(acc[p], lo, hi);
                g_gate[b0r * NE + jj0 + tx] = sigf(lo + bv);
                g_gate[(b0r + 1) * NE + jj0 + tx] = sigf(hi + bv);
            }
        }
    } else {
        int j0 = (bx - 40) * 64;
        gemm64<false, 16>(h, ND, Whh + (size_t)j0 * ND, ND, 64, wact, acc, Xs, Ws, tid);
        if (wact) {
#pragma unroll
            for (int p = 0; p < 4; p++) {
                int b0r = ty * 8 + 2 * p;
                float lo, hi; unpack2(acc[p], lo, hi);
                g_gxh_h[b0r * (4 * ND) + j0 + tx] = lo;
                g_gxh_h[(b0r + 1) * (4 * ND) + j0 + tx] = hi;
            }
        }
    }
}

// phase2: one block per b — alpha softmax + awe (512 threads)
__device__ void phase2(int b, int t, const float* __restrict__ fullw,
                       const float* __restrict__ fullb, const float* __restrict__ enc,
                       float* __restrict__ out, const int* sD, const int* sO) {
    __shared__ float att2s[NA];
    __shared__ float ws[NA];
    __shared__ float ev[NP];
    __shared__ float al[NP + 2];
    __shared__ float red[16];
    __shared__ float smax, ssum;
    const int tid = threadIdx.x, warp = tid >> 5, lane = tid & 31;
    float* aout = out + OUT_ALPHA + ((size_t)b * NT + t) * NP;
    if (t >= sD[b]) {
        if (tid < NP) aout[tid] = 0.f;
        return;
    }
    att2s[tid] = g_att2[b * NA + tid];  // tid covers 512 exactly? tid<512, NA=512
    ws[tid] = fullw[tid];
    __syncthreads();
    const float fb = fullb[0];
    for (int p = warp; p < NP; p += 16) {
        const float* a1 = g_att1 + ((size_t)(b * NP + p)) * NA;
        float s = 0.f;
#pragma unroll 4
        for (int a = lane; a < NA; a += 32) {
            float v = a1[a] + att2s[a];
            s += fmaxf(v, 0.f) * ws[a];
        }
#pragma unroll
        for (int o = 16; o; o >>= 1) s += __shfl_xor_sync(0xffffffffu, s, o);
        if (lane == 0) ev[p] = s + fb;
    }
    __syncthreads();
    float v = (tid < NP) ? ev[tid] : -3.0e38f;
    float m = v;
#pragma unroll
    for (int o = 16; o; o >>= 1) m = fmaxf(m, __shfl_xor_sync(0xffffffffu, m, o));
    if (lane == 0) red[warp] = m;
    __syncthreads();
    if (tid == 0) { float mm = red[0]; for (int i = 1; i < 16; i++) mm = fmaxf(mm, red[i]); smax = mm; }
    __syncthreads();
    float ex = (tid < NP) ? expf(v - smax) : 0.f;
    float s2 = ex;
#pragma unroll
    for (int o = 16; o; o >>= 1) s2 += __shfl_xor_sync(0xffffffffu, s2, o);
    if (lane == 0) red[warp] = s2;
    __syncthreads();
    if (tid == 0) { float ss = 0.f; for (int i = 0; i < 16; i++) ss += red[i]; ssum = ss; }
    __syncthreads();
    if (tid < NP) {
        float a = ex / ssum;
        al[tid] = a;
        aout[tid] = a;
    }
    if (tid >= NP && tid < NP + 2) al[tid] = 0.f;
    __syncthreads();
    const int e0 = tid * 4;
    const float* eb = enc + (size_t)sO[b] * NP * NE + e0;
    float4 aw = {0.f, 0.f, 0.f, 0.f};
    for (int p = 0; p < NP; p += 2) {
        float a0 = al[p], a1 = al[p + 1];
        const float4 r0 = *(const float4*)(eb + (size_t)p * NE);
        const float4 r1 = *(const float4*)(eb + (size_t)(p + 1) * NE);
        aw.x += a0 * r0.x + a1 * r1.x; aw.y += a0 * r0.y + a1 * r1.y;
        aw.z += a0 * r0.z + a1 * r1.z; aw.w += a0 * r0.w + a1 * r1.w;
    }
    const float4 g = *(const float4*)&g_gate[b * NE + e0];
    float4 o0 = {aw.x * g.x, aw.y * g.y, aw.z * g.z, aw.w * g.w};
    *(float4*)&g_awe[b * NE + e0] = o0;
}

// phase3: gawe — 128 tiles: j0 = (bid&31)*64, ks = bid>>5 (4-way K=512 split)
__device__ void phase3(int bid, int t, const float* __restrict__ Wih,
                       float* Xs, float* Ws, const int* sD, int tid) {
    const int tx = tid & 63, ty = tid >> 6;
    const int j0 = (bid & 31) * 64;
    const int ks = bid >> 5;
    const bool wact = (t < sD[ty * 8]);
    ull acc[4] = {};
    gemm64<false, 16>(g_awe + ks * 512, NE, Wih + (size_t)j0 * NX + 512 + ks * 512, NX, 64,
                      wact, acc, Xs, Ws, tid);
    if (wact) {
#pragma unroll
        for (int p = 0; p < 4; p++) {
            int b0r = ty * 8 + 2 * p;
            float lo, hi; unpack2(acc[p], lo, hi);
            g_gawe[ks][b0r * (4 * ND) + j0 + tx] = lo;
            g_gawe[ks][(b0r + 1) * (4 * ND) + j0 + tx] = hi;
        }
    }
}

// phase4: lstm (512 threads, d = tid)
__device__ void phase4(int b, int t, const int* sD) {
    if (t >= sD[b]) return;
    const int d = threadIdx.x;
    float gv[4];
#pragma unroll
    for (int q = 0; q < 4; q++) {
        int j = q * ND + d;
        float s = g_embg[t][b * (4 * ND) + j] + g_gxh_h[b * (4 * ND) + j];
#pragma unroll
        for (int ks = 0; ks < 4; ks++) s += g_gawe[ks][b * (4 * ND) + j];
        gv[q] = s;
    }
    float i_ = sigf(gv[0]);
    float f_ = sigf(gv[1]);
    float gg = tanhf(gv[2]);
    float o_ = sigf(gv[3]);
    float c = f_ * g_c[b * ND + d] + i_ * gg;
    g_c[b * ND + d] = c;
    g_h[(t & 1) ^ 1][b * ND + d] = o_ * tanhf(c);
}

// ---------------------------------------------------------------
// Persistent loop: 148 blocks x 512 threads.
// ---------------------------------------------------------------
__global__ __launch_bounds__(512) void k_loop(
        const float* __restrict__ enc,
        const float* __restrict__ attW, const float* __restrict__ attb,
        const float* __restrict__ fbW,  const float* __restrict__ fbb,
        const float* __restrict__ fullw, const float* __restrict__ fullb,
        const float* __restrict__ Wih,  const float* __restrict__ Whh,
        const float* __restrict__ fcW,  const float* __restrict__ fcb,
        float* __restrict__ out) {
    extern __shared__ float dyn[];
    float* Xs = dyn;
    float* Ws = dyn + 2 * X64;
    __shared__ int sD[NB], sO[NB];
    const int bid = blockIdx.x, tid = threadIdx.x;
    unsigned gen = g_gen;
    if (tid < NB) { sD[tid] = g_declen[tid]; sO[tid] = g_order[tid]; }
    __syncthreads();

    for (int t = 0; t <= NT; t++) {
        // ---- P1: att2/gate/gates-h on bids 0-71; fc tiles 0-75 on 72-147 ----
        if (bid < 72) {
            if (t < NT) p1_tile(bid, t, attW, attb, fbW, fbb, Whh, Xs, Ws, sD, tid);
        } else {
            if (t >= 1) fc_tile(bid - 72, t - 1, g_h[t & 1], fcW, fcb, out, Xs, Ws, sD, tid);
        }
        gridbar(gen);
        // ---- P2 window: alpha+awe on 0-63; fc tiles 76-156 on 64-147 ----
        if (bid < 64) {
            if (t < NT) phase2(bid, t, fullw, fullb, enc, out, sD, sO);
        } else {
            int tile = 76 + (bid - 64);
            if (t >= 1 && tile < 157)
                fc_tile(tile, t - 1, g_h[t & 1], fcW, fcb, out, Xs, Ws, sD, tid);
        }
        if (t == NT) break;
        gridbar(gen);
        // ---- P3: gawe (128 tiles) ----
        if (bid < 128) phase3(bid, t, Wih, Xs, Ws, sD, tid);
        gridbar(gen);
        // ---- P4: lstm ----
        if (bid < NB) phase4(bid, t, sD);
        gridbar(gen);
    }
}

// ---------------------------------------------------------------
extern "C" void kernel_launch(void* const* d_in, const int* in_sizes, int n_in,
                              void* d_out, int out_size) {
    (void)in_sizes; (void)n_in; (void)out_size;
    const float* enc     = (const float*)d_in[0];
    const int*   caps    = (const int*)d_in[1];
    const int*   clen    = (const int*)d_in[2];
    const float* embW    = (const float*)d_in[3];
    const float* attEncW = (const float*)d_in[4];
    const float* attEncB = (const float*)d_in[5];
    const float* attDecW = (const float*)d_in[6];
    const float* attDecB = (const float*)d_in[7];
    const float* fullW   = (const float*)d_in[8];
    const float* fullB   = (const float*)d_in[9];
    const float* Wih     = (const float*)d_in[10];
    const float* Whh     = (const float*)d_in[11];
    const float* bih     = (const float*)d_in[12];
    const float* bhh     = (const float*)d_in[13];
    const float* iHW     = (const float*)d_in[14];
    const float* iHb     = (const float*)d_in[15];
    const float* iCW     = (const float*)d_in[16];
    const float* iCb     = (const float*)d_in[17];
    const float* fbW     = (const float*)d_in[18];
    const float* fbb     = (const float*)d_in[19];
    const float* fcW     = (const float*)d_in[20];
    const float* fcb     = (const float*)d_in[21];
    float* out = (float*)d_out;

    const int SM_G128 = (2 * XS_ST + 2 * WS_ST) * 4;   // 51200
    const int SM_ATT1 = (4 * AXS_ST) * 4;              // 67584
    const int SM_LOOP = (2 * X64 + 2 * W64) * 4;       // 34816
    static int configured = 0;
    if (!configured) {
        cudaFuncSetAttribute(k_init, cudaFuncAttributeMaxDynamicSharedMemorySize, SM_G128);
        cudaFuncSetAttribute(k_embg, cudaFuncAttributeMaxDynamicSharedMemorySize, SM_G128);
        cudaFuncSetAttribute(k_att1, cudaFuncAttributeMaxDynamicSharedMemorySize, SM_ATT1);
        cudaFuncSetAttribute(k_loop, cudaFuncAttributeMaxDynamicSharedMemorySize, SM_LOOP);
        configured = 1;
    }

    k_sort<<<1, 64>>>(clen, caps, out);
    k_prep<<<512 + NT * NB, 256>>>(caps, embW, enc);
    k_init<<<32, 256, SM_G128>>>(iHW, iCW, iHb, iCb);
    k_embg<<<NT * 16, 256, SM_G128>>>(Wih, bih, bhh);
    k_att1<<<dim3(4, 98), 256, SM_ATT1>>>(enc, attEncW, attEncB);
    k_loop<<<NBLK, 512, SM_LOOP>>>(enc, attDecW, attDecB, fbW, fbb,
                                   fullW, fullB, Wih, Whh, fcW, fcb, out);
}

// round 11
// speedup vs baseline: 2.8004x; 1.0156x over previous
#include <cuda_runtime.h>
#include <math.h>

#define NB 64
#define NP 196
#define NE 2048
#define ND 512
#define NA 512
#define NEMB 512
#define NV 10000
#define NL 52
#define NT 51
#define NX 2560
#define NBLK 148

#define OUT_PRED   0
#define OUT_CAPS   32640000
#define OUT_DECLEN 32643328
#define OUT_ALPHA  32643392
#define OUT_ORDER  33283136

typedef unsigned long long ull;

// ---- scratch ----
__device__ int   g_order[NB];
__device__ int   g_declen[NB];
__device__ float g_att1[(size_t)NB * NP * NA];
__device__ float g_h[2][NB * ND];
__device__ float g_c[NB * ND];
__device__ float g_att2p[2][NB * NA];         // att2 K-split partials (bias in ks0)
__device__ float g_gatep[2][NB * NE];         // gate pre-sigmoid partials (bias in ks0)
__device__ float g_awe[NB * NE];
__device__ float g_embT[NT][NB][NEMB];
__device__ float g_embg[NT][NB * 4 * ND];     // emb@Wih[:, :512]^T + biases
__device__ float g_gawe[8][NB * 4 * ND];      // [h;awe]@[Whh;Wih_awe]^T K-split partials
__device__ float g_mean[NB * NE];
__device__ float g_initp[4][NB * 1024];

// ---- barrier state ----
__device__ unsigned g_cnt;
__device__ volatile unsigned g_gen;
__device__ unsigned g_icnt;

__device__ __forceinline__ float sigf(float x) { return 1.f / (1.f + expf(-x)); }

__device__ __forceinline__ ull pack2(float x, float y) {
    ull d; asm("mov.b64 %0, {%1, %2};" : "=l"(d) : "f"(x), "f"(y)); return d;
}
__device__ __forceinline__ void fma2(ull& d, ull a, ull b) {
    asm("fma.rn.f32x2 %0, %1, %2, %0;" : "+l"(d) : "l"(a), "l"(b));
}
__device__ __forceinline__ void unpack2(ull v, float& lo, float& hi) {
    asm("mov.b64 {%0, %1}, %2;" : "=f"(lo), "=f"(hi) : "l"(v));
}
__device__ __forceinline__ void cpa4(void* dst, const void* src) {
    unsigned sd = (unsigned)__cvta_generic_to_shared(dst);
    asm volatile("cp.async.ca.shared.global [%0], [%1], 4;" :: "r"(sd), "l"(src));
}
#define CP_COMMIT asm volatile("cp.async.commit_group;")
#define CP_WAIT1  asm volatile("cp.async.wait_group 1;")
#define CP_WAIT0  asm volatile("cp.async.wait_group 0;")

__device__ __forceinline__ void gridbar(unsigned& gen) {
    __threadfence();
    __syncthreads();
    if (threadIdx.x == 0) {
        if (atomicAdd(&g_cnt, 1u) == NBLK - 1) {
            atomicExch(&g_cnt, 0u);
            __threadfence();
            g_gen = gen + 1;
        } else {
            while (g_gen == gen) __nanosleep(32);
        }
    }
    __syncthreads();
    gen++;
}

// ===============================================================
// 512-thread 64b x 128j micro-kernel. Thread = 8 rows x 2 cols
// (tx, tx+64). Per kk per warp: 2 bcast LDS.128 + 2 LDS.32 + 8 fma2
// -> per SM 64 LDS-cyc vs 64 fma-cyc (balanced).
// Xs[k][b] stride 68, Ws[k][j] stride 132.
// ===============================================================
#define XS_ST 2176   // 32*68
#define WS_ST 4224   // 32*132
__device__ __forceinline__ void compute128(const float* Xs, const float* Ws, int tid,
                                           ull aA[4], ull aB[4]) {
    const int tx = tid & 63, ty = tid >> 6;
#pragma unroll
    for (int kk = 0; kk < 32; kk++) {
        const float4 xa = *(const float4*)(Xs + kk * 68 + ty * 8);
        const float4 xb = *(const float4*)(Xs + kk * 68 + ty * 8 + 4);
        const float w0 = Ws[kk * 132 + tx];
        const float w1 = Ws[kk * 132 + 64 + tx];
        ull W0 = pack2(w0, w0), W1 = pack2(w1, w1);
        ull a0 = ((const ull*)&xa)[0], a1 = ((const ull*)&xa)[1];
        ull a2 = ((const ull*)&xb)[0], a3 = ((const ull*)&xb)[1];
        fma2(aA[0], a0, W0); fma2(aA[1], a1, W0); fma2(aA[2], a2, W0); fma2(aA[3], a3, W0);
        fma2(aB[0], a0, W1); fma2(aB[1], a1, W1); fma2(aB[2], a2, W1); fma2(aB[3], a3, W1);
    }
}

// K-major W (weights stored [k][j], j contiguous). NCH chunks from kbase.
template<int NCH>
__device__ __forceinline__ void run_kmajor(
    const float* __restrict__ Xg, int xstride,
    const float* __restrict__ Wg, size_t wstride, int vw, int kbase,
    bool wact, ull aA[4], ull aB[4], float* Xs, float* Ws, int tid)
{
    auto stage = [&](int c, int st) {
        int k0 = kbase + (c << 5);
#pragma unroll
        for (int i = 0; i < 4; i++) {
            int idx = (i << 9) + tid;
            int k = idx & 31, b = idx >> 5;
            cpa4(&Xs[st * XS_ST + k * 68 + b], Xg + (size_t)b * xstride + k0 + k);
        }
#pragma unroll
        for (int i = 0; i < 8; i++) {
            int idx = (i << 9) + tid;
            int j = idx & 127, k = idx >> 7;
            int jc = (j < vw) ? j : 0;
            cpa4(&Ws[st * WS_ST + k * 132 + j], Wg + (size_t)(k0 + k) * wstride + jc);
        }
        CP_COMMIT;
    };
    stage(0, 0);
    for (int c = 0; c < NCH; c++) {
        int st = c & 1;
        if (c < NCH - 1) { stage(c + 1, st ^ 1); CP_WAIT1; }
        else            { CP_WAIT0; }
        __syncthreads();
        if (wact) compute128(Xs + st * XS_ST, Ws + st * WS_ST, tid, aA, aB);
        __syncthreads();
    }
}

// Mixed X=[h;awe], W=[Whh;Wih_awe] (both j-major, split at k=512).
// Whh_j0 = Whh + j0*ND, Wih_j0 = Wih + j0*NX. kbase in [0,2560).
template<int NCH>
__device__ __forceinline__ void run_mix(
    const float* __restrict__ h, const float* __restrict__ awe,
    const float* __restrict__ Whh_j0, const float* __restrict__ Wih_j0,
    int kbase, bool wact, ull aA[4], ull aB[4], float* Xs, float* Ws, int tid)
{
    auto stage = [&](int c, int st) {
        int k0 = kbase + (c << 5);
#pragma unroll
        for (int i = 0; i < 4; i++) {
            int idx = (i << 9) + tid;
            int k = idx & 31, b = idx >> 5;
            int gk = k0 + k;
            const float* src = (gk < ND) ? (h + (size_t)b * ND + gk)
                                         : (awe + (size_t)b * NE + gk - ND);
            cpa4(&Xs[st * XS_ST + k * 68 + b], src);
        }
#pragma unroll
        for (int i = 0; i < 8; i++) {
            int idx = (i << 9) + tid;
            int k = idx & 31, j = idx >> 5;
            int gk = k0 + k;
            const float* src = (gk < ND) ? (Whh_j0 + (size_t)j * ND + gk)
                                         : (Wih_j0 + (size_t)j * NX + gk);
            cpa4(&Ws[st * WS_ST + k * 132 + j], src);
        }
        CP_COMMIT;
    };
    stage(0, 0);
    for (int c = 0; c < NCH; c++) {
        int st = c & 1;
        if (c < NCH - 1) { stage(c + 1, st ^ 1); CP_WAIT1; }
        else            { CP_WAIT0; }
        __syncthreads();
        if (wact) compute128(Xs + st * XS_ST, Ws + st * WS_ST, tid, aA, aB);
        __syncthreads();
    }
}

// ===============================================================
// 256-thread 64b x 128j GEMM (prologue kernels only)
// ===============================================================
template<bool KMAJOR, int NCH>
__device__ __forceinline__ void gemm_acc(
    const float* __restrict__ Xg, int xstride,
    const float* __restrict__ Wg, size_t wstride, int vw,
    bool wact, ull acc[4][4], float* Xs, float* Ws, int tid)
{
    const int tx = tid & 31, ty = tid >> 5;
    auto stage = [&](int k0, int st) {
#pragma unroll
        for (int i = 0; i < 8; i++) {
            int idx = (i << 8) + tid;
            int k = idx & 31, b = idx >> 5;
            cpa4(&Xs[st * XS_ST + k * 68 + b], Xg + (size_t)b * xstride + k0 + k);
        }
#pragma unroll
        for (int i = 0; i < 16; i++) {
            int idx = (i << 8) + tid;
            int j = KMAJOR ? (idx & 127) : (idx >> 5);
            int k = KMAJOR ? (idx >> 7) : (idx & 31);
            int jc = (j < vw) ? j : 0;
            const float* src = KMAJOR ? (Wg + (size_t)(k0 + k) * wstride + jc)
                                      : (Wg + (size_t)jc * wstride + k0 + k);
            cpa4(&Ws[st * WS_ST + k * 132 + j], src);
        }
        CP_COMMIT;
    };
    stage(0, 0);
    for (int c = 0; c < NCH; c++) {
        int st = c & 1;
        if (c < NCH - 1) { stage((c + 1) << 5, st ^ 1); CP_WAIT1; }
        else            { CP_WAIT0; }
        __syncthreads();
        if (wact) {
#pragma unroll
            for (int kk = 0; kk < 32; kk++) {
                const float4 xa = *(const float4*)(Xs + st * XS_ST + kk * 68 + ty * 8);
                const float4 xb = *(const float4*)(Xs + st * XS_ST + kk * 68 + ty * 8 + 4);
                const float4 wv = *(const float4*)(Ws + st * WS_ST + kk * 132 + tx * 4);
                ull a0 = ((const ull*)&xa)[0], a1 = ((const ull*)&xa)[1];
                ull a2 = ((const ull*)&xb)[0], a3 = ((const ull*)&xb)[1];
                ull w0 = pack2(wv.x, wv.x), w1 = pack2(wv.y, wv.y);
                ull w2 = pack2(wv.z, wv.z), w3 = pack2(wv.w, wv.w);
                fma2(acc[0][0], a0, w0); fma2(acc[0][1], a0, w1);
                fma2(acc[0][2], a0, w2); fma2(acc[0][3], a0, w3);
                fma2(acc[1][0], a1, w0); fma2(acc[1][1], a1, w1);
                fma2(acc[1][2], a1, w2); fma2(acc[1][3], a1, w3);
                fma2(acc[2][0], a2, w0); fma2(acc[2][1], a2, w1);
                fma2(acc[2][2], a2, w2); fma2(acc[2][3], a2, w3);
                fma2(acc[3][0], a3, w0); fma2(acc[3][1], a3, w1);
                fma2(acc[3][2], a3, w2); fma2(acc[3][3], a3, w3);
            }
        }
        __syncthreads();
    }
}

// ---------------------------------------------------------------
__global__ void k_sort(const int* __restrict__ clen, const int* __restrict__ caps,
                       float* __restrict__ out) {
    int i = threadIdx.x;
    __shared__ int len[NB];
    if (i < NB) len[i] = clen[i];
    __syncthreads();
    if (i < NB) {
        int li = len[i], r = 0;
        for (int j = 0; j < NB; j++) {
            int lj = len[j];
            if (lj > li || (lj == li && j < i)) r++;
        }
        g_order[r] = i;
    }
    __syncthreads();
    if (i < NB) {
        int src = g_order[i];
        int dl = len[src] - 1;
        g_declen[i] = dl;
        out[OUT_DECLEN + i] = (float)dl;
        out[OUT_ORDER + i] = (float)src;
        for (int t = 0; t < NL; t++)
            out[OUT_CAPS + i * NL + t] = (float)caps[src * NL + t];
    }
}

__global__ void k_prep(const int* __restrict__ caps, const float* __restrict__ embW,
                       const float* __restrict__ enc) {
    const int bx = blockIdx.x, tid = threadIdx.x;
    if (bx < 512) {
        int b = bx >> 3;
        int e = (bx & 7) * 256 + tid;
        const float* base = enc + (size_t)g_order[b] * NP * NE + e;
        float s = 0.f;
#pragma unroll 7
        for (int p = 0; p < NP; p++) s += base[(size_t)p * NE];
        g_mean[b * NE + e] = s * (1.0f / NP);
    } else {
        int idx = bx - 512;
        int tt = idx >> 6, b = idx & 63;
        int cap = caps[g_order[b] * NL + tt];
        for (int i = tid; i < NEMB; i += 256)
            g_embT[tt][b][i] = embW[(size_t)cap * NEMB + i];
    }
}

// emb-gates for ALL steps: grid 51*16
__global__ __launch_bounds__(256) void k_embg(const float* __restrict__ Wih,
                                              const float* __restrict__ bih,
                                              const float* __restrict__ bhh) {
    extern __shared__ float dyn[];
    float* Xs = dyn;
    float* Ws = dyn + 2 * XS_ST;
    const int tid = threadIdx.x, tx = tid & 31, ty = tid >> 5;
    const int t = blockIdx.x >> 4;
    const int j0 = (blockIdx.x & 15) * 128;
    ull acc[4][4] = {};
    gemm_acc<false, 16>(&g_embT[t][0][0], NEMB, Wih + (size_t)j0 * NX, NX, 128,
                        true, acc, Xs, Ws, tid);
#pragma unroll
    for (int p = 0; p < 4; p++) {
        int b0r = ty * 8 + 2 * p;
        const float4 b1 = *(const float4*)&bih[j0 + tx * 4];
        const float4 b2 = *(const float4*)&bhh[j0 + tx * 4];
        float4 lov, hiv;
        unpack2(acc[p][0], lov.x, hiv.x); unpack2(acc[p][1], lov.y, hiv.y);
        unpack2(acc[p][2], lov.z, hiv.z); unpack2(acc[p][3], lov.w, hiv.w);
        lov.x += b1.x + b2.x; lov.y += b1.y + b2.y; lov.z += b1.z + b2.z; lov.w += b1.w + b2.w;
        hiv.x += b1.x + b2.x; hiv.y += b1.y + b2.y; hiv.z += b1.z + b2.z; hiv.w += b1.w + b2.w;
        *(float4*)&g_embg[t][b0r * (4 * ND) + j0 + tx * 4] = lov;
        *(float4*)&g_embg[t][(b0r + 1) * (4 * ND) + j0 + tx * 4] = hiv;
    }
}

// h0/c0 split-K GEMM + combine
__global__ __launch_bounds__(256) void k_init(const float* __restrict__ HW,
                                              const float* __restrict__ CW,
                                              const float* __restrict__ Hb,
                                              const float* __restrict__ Cb) {
    extern __shared__ float dyn[];
    __shared__ int lastf;
    float* Xs = dyn;
    float* Ws = dyn + 2 * XS_ST;
    const int tid = threadIdx.x, tx = tid & 31, ty = tid >> 5;
    const int j0 = (blockIdx.x & 7) * 128, ks = blockIdx.x >> 3;
    const float* W = (j0 < 512) ? (HW + j0) : (CW + j0 - 512);
    ull acc[4][4] = {};
    gemm_acc<true, 16>(g_mean + ks * 512, NE, W + (size_t)ks * 512 * ND, ND, 128,
                       true, acc, Xs, Ws, tid);
#pragma unroll
    for (int p = 0; p < 4; p++) {
        int b0r = ty * 8 + 2 * p;
        float4 lov, hiv;
        unpack2(acc[p][0], lov.x, hiv.x); unpack2(acc[p][1], lov.y, hiv.y);
        unpack2(acc[p][2], lov.z, hiv.z); unpack2(acc[p][3], lov.w, hiv.w);
        *(float4*)&g_initp[ks][b0r * 1024 + j0 + tx * 4] = lov;
        *(float4*)&g_initp[ks][(b0r + 1) * 1024 + j0 + tx * 4] = hiv;
    }
    __threadfence();
    __syncthreads();
    if (tid == 0) lastf = (atomicAdd(&g_icnt, 1u) == 31);
    __syncthreads();
    if (lastf) {
        __threadfence();
        for (int i = tid; i < NB * 1024; i += 256) {
            int b = i >> 10, j = i & 1023;
            float s = g_initp[0][i] + g_initp[1][i] + g_initp[2][i] + g_initp[3][i];
            if (j < 512) g_h[0][b * ND + j] = s + Hb[j];
            else         g_c[b * ND + j - 512] = s + Cb[j - 512];
        }
        if (tid == 0) atomicExch(&g_icnt, 0u);
    }
}

// att1 standalone: 128m x 128n, K=2048, grid (4,98)
#define AXS_ST 4224
__global__ __launch_bounds__(256) void k_att1(const float* __restrict__ enc,
                                              const float* __restrict__ W,
                                              const float* __restrict__ bias) {
    extern __shared__ float dyn[];
    float* Xs = dyn;
    float* Ws = dyn + 2 * AXS_ST;
    __shared__ int rowBase[128];
    const int bn = blockIdx.x, bm = blockIdx.y, tid = threadIdx.x;
    const int row0 = bm * 128;
    if (tid < 128) {
        int m = row0 + tid;
        rowBase[tid] = g_order[m / NP] * NP + (m % NP);
    }
    __syncthreads();
    const int tx = tid & 31, ty = tid >> 5;
    ull acc[8][4] = {};
    auto stage = [&](int k0, int st) {
#pragma unroll
        for (int i = 0; i < 16; i++) {
            int idx = (i << 8) + tid;
            int k = idx & 31, m = idx >> 5;
            cpa4(&Xs[st * AXS_ST + k * 132 + m], enc + (size_t)rowBase[m] * NE + k0 + k);
        }
#pragma unroll
        for (int i = 0; i < 16; i++) {
            int idx = (i << 8) + tid;
            int j = idx & 127, k = idx >> 7;
            cpa4(&Ws[st * AXS_ST + k * 132 + j], W + (size_t)(k0 + k) * NA + bn * 128 + j);
        }
        CP_COMMIT;
    };
    stage(0, 0);
    for (int c = 0; c < 64; c++) {
        int st = c & 1;
        if (c < 63) { stage((c + 1) << 5, st ^ 1); CP_WAIT1; }
        else        { CP_WAIT0; }
        __syncthreads();
#pragma unroll
        for (int kk = 0; kk < 32; kk++) {
            const float* xrow = Xs + st * AXS_ST + kk * 132 + ty * 16;
            const float4 x0 = *(const float4*)(xrow);
            const float4 x1 = *(const float4*)(xrow + 4);
            const float4 x2 = *(const float4*)(xrow + 8);
            const float4 x3 = *(const float4*)(xrow + 12);
            const float4 wv = *(const float4*)(Ws + st * AXS_ST + kk * 132 + tx * 4);
            ull a[8];
            a[0] = ((const ull*)&x0)[0]; a[1] = ((const ull*)&x0)[1];
            a[2] = ((const ull*)&x1)[0]; a[3] = ((const ull*)&x1)[1];
            a[4] = ((const ull*)&x2)[0]; a[5] = ((const ull*)&x2)[1];
            a[6] = ((const ull*)&x3)[0]; a[7] = ((const ull*)&x3)[1];
            ull w0 = pack2(wv.x, wv.x), w1 = pack2(wv.y, wv.y);
            ull w2 = pack2(wv.z, wv.z), w3 = pack2(wv.w, wv.w);
#pragma unroll
            for (int p = 0; p < 8; p++) {
                fma2(acc[p][0], a[p], w0); fma2(acc[p][1], a[p], w1);
                fma2(acc[p][2], a[p], w2); fma2(acc[p][3], a[p], w3);
            }
        }
        __syncthreads();
    }
    const float4 bv = *(const float4*)&bias[bn * 128 + tx * 4];
#pragma unroll
    for (int p = 0; p < 8; p++) {
        float4 lov, hiv;
        unpack2(acc[p][0], lov.x, hiv.x); unpack2(acc[p][1], lov.y, hiv.y);
        unpack2(acc[p][2], lov.z, hiv.z); unpack2(acc[p][3], lov.w, hiv.w);
        lov.x += bv.x; lov.y += bv.y; lov.z += bv.z; lov.w += bv.w;
        hiv.x += bv.x; hiv.y += bv.y; hiv.z += bv.z; hiv.w += bv.w;
        size_t m0 = row0 + ty * 16 + 2 * p;
        *(float4*)&g_att1[m0 * NA + bn * 128 + tx * 4] = lov;
        *(float4*)&g_att1[(m0 + 1) * NA + bn * 128 + tx * 4] = hiv;
    }
}

// ---------------------------------------------------------------
// alpha softmax + awe (512 threads, one block per b)
// ---------------------------------------------------------------
__device__ void alpha_awe(int b, int t, const float* __restrict__ fullw,
                          const float* __restrict__ fullb, const float* __restrict__ enc,
                          float* __restrict__ out, const int* sD, const int* sO) {
    __shared__ float att2s[NA];
    __shared__ float ws[NA];
    __shared__ float ev[NP];
    __shared__ float al[NP + 2];
    __shared__ float red[16];
    __shared__ float smax, ssum;
    const int tid = threadIdx.x, warp = tid >> 5, lane = tid & 31;
    float* aout = out + OUT_ALPHA + ((size_t)b * NT + t) * NP;
    if (t >= sD[b]) {
        if (tid < NP) aout[tid] = 0.f;
        return;
    }
    att2s[tid] = g_att2p[0][b * NA + tid] + g_att2p[1][b * NA + tid];
    ws[tid] = fullw[tid];
    __syncthreads();
    const float fb = fullb[0];
    for (int p = warp; p < NP; p += 16) {
        const float* a1 = g_att1 + ((size_t)(b * NP + p)) * NA;
        float s = 0.f;
#pragma unroll 4
        for (int a = lane; a < NA; a += 32) {
            float v = a1[a] + att2s[a];
            s += fmaxf(v, 0.f) * ws[a];
        }
#pragma unroll
        for (int o = 16; o; o >>= 1) s += __shfl_xor_sync(0xffffffffu, s, o);
        if (lane == 0) ev[p] = s + fb;
    }
    __syncthreads();
    float v = (tid < NP) ? ev[tid] : -3.0e38f;
    float m = v;
#pragma unroll
    for (int o = 16; o; o >>= 1) m = fmaxf(m, __shfl_xor_sync(0xffffffffu, m, o));
    if (lane == 0) red[warp] = m;
    __syncthreads();
    if (tid == 0) { float mm = red[0]; for (int i = 1; i < 16; i++) mm = fmaxf(mm, red[i]); smax = mm; }
    __syncthreads();
    float ex = (tid < NP) ? expf(v - smax) : 0.f;
    float s2 = ex;
#pragma unroll
    for (int o = 16; o; o >>= 1) s2 += __shfl_xor_sync(0xffffffffu, s2, o);
    if (lane == 0) red[warp] = s2;
    __syncthreads();
    if (tid == 0) { float ss = 0.f; for (int i = 0; i < 16; i++) ss += red[i]; ssum = ss; }
    __syncthreads();
    if (tid < NP) {
        float a = ex / ssum;
        al[tid] = a;
        aout[tid] = a;
    }
    if (tid >= NP && tid < NP + 2) al[tid] = 0.f;
    __syncthreads();
    const int e0 = tid * 4;
    const float* eb = enc + (size_t)sO[b] * NP * NE + e0;
    float4 aw = {0.f, 0.f, 0.f, 0.f};
    for (int p = 0; p < NP; p += 2) {
        float a0 = al[p], a1 = al[p + 1];
        const float4 r0 = *(const float4*)(eb + (size_t)p * NE);
        const float4 r1 = *(const float4*)(eb + (size_t)(p + 1) * NE);
        aw.x += a0 * r0.x + a1 * r1.x; aw.y += a0 * r0.y + a1 * r1.y;
        aw.z += a0 * r0.z + a1 * r1.z; aw.w += a0 * r0.w + a1 * r1.w;
    }
    const float4 gp0 = *(const float4*)&g_gatep[0][b * NE + e0];
    const float4 gp1 = *(const float4*)&g_gatep[1][b * NE + e0];
    float4 o0;
    o0.x = aw.x * sigf(gp0.x + gp1.x);
    o0.y = aw.y * sigf(gp0.y + gp1.y);
    o0.z = aw.z * sigf(gp0.z + gp1.z);
    o0.w = aw.w * sigf(gp0.w + gp1.w);
    *(float4*)&g_awe[b * NE + e0] = o0;
}

// ---------------------------------------------------------------
// Persistent loop: 148 blocks x 512 threads.
//  W1: att2 (bid 0-7: jt=bid>>1, ks=bid&1), gate (bid 8-39),
//      fc(t-1) chunks 0-7 (bid 40-118)
//  W2: fc chunks 8-15 + writeout (bid 40-118), alpha (bid<40 -> b=bid;
//      bid 119-142 -> b=bid-79)
//  W3: merged gates [h;awe]@[Whh;Wih]^T: 128 tiles (jt=bid&15, ks=bid>>4)
//  W4: lstm (bid<64)
// ---------------------------------------------------------------
__global__ __launch_bounds__(512) void k_loop(
        const float* __restrict__ enc,
        const float* __restrict__ attW, const float* __restrict__ attb,
        const float* __restrict__ fbW,  const float* __restrict__ fbb,
        const float* __restrict__ fullw, const float* __restrict__ fullb,
        const float* __restrict__ Wih,  const float* __restrict__ Whh,
        const float* __restrict__ fcW,  const float* __restrict__ fcb,
        float* __restrict__ out) {
    extern __shared__ float dyn[];
    float* Xs = dyn;
    float* Ws = dyn + 2 * XS_ST;
    __shared__ int sD[NB], sO[NB];
    const int bid = blockIdx.x, tid = threadIdx.x;
    const int tx = tid & 63, ty = tid >> 6;
    unsigned gen = g_gen;
    if (tid < NB) { sD[tid] = g_declen[tid]; sO[tid] = g_order[tid]; }
    __syncthreads();

    for (int t = 0; t <= NT; t++) {
        const float* h = g_h[t & 1];
        const bool wact = (t < sD[ty * 8]);
        ull fA[4] = {}, fB[4] = {};
        const bool isfc = (bid >= 40 && bid < 119);
        const int fct = bid - 40;               // fc tile 0..78
        const int fj0 = fct * 128;
        const int fvw = (NV - fj0 > 128) ? 128 : (NV - fj0);
        const bool fcact = isfc && (t >= 1);
        const bool fwact = (t - 1 < sD[ty * 8]);

        // ---------------- W1 ----------------
        if (t < NT && bid < 8) {
            int jt = bid >> 1, ks = bid & 1, j0 = jt * 128;
            ull aA[4] = {}, aB[4] = {};
            run_kmajor<8>(h, ND, attW + j0, NA, 128, ks * 256, wact, aA, aB, Xs, Ws, tid);
            if (wact) {
                float bvA = (ks == 0) ? attb[j0 + tx] : 0.f;
                float bvB = (ks == 0) ? attb[j0 + 64 + tx] : 0.f;
#pragma unroll
                for (int p = 0; p < 4; p++) {
                    int bA = ty * 8 + 2 * p;
                    float lo, hi;
                    unpack2(aA[p], lo, hi);
                    g_att2p[ks][bA * NA + j0 + tx] = lo + bvA;
                    g_att2p[ks][(bA + 1) * NA + j0 + tx] = hi + bvA;
                    unpack2(aB[p], lo, hi);
                    g_att2p[ks][bA * NA + j0 + 64 + tx] = lo + bvB;
                    g_att2p[ks][(bA + 1) * NA + j0 + 64 + tx] = hi + bvB;
                }
            }
        } else if (t < NT && bid < 40) {
            int idx = bid - 8;
            int jt = idx >> 1, ks = idx & 1, j0 = jt * 128;
            ull aA[4] = {}, aB[4] = {};
            run_kmajor<8>(h, ND, fbW + j0, NE, 128, ks * 256, wact, aA, aB, Xs, Ws, tid);
            if (wact) {
                float bvA = (ks == 0) ? fbb[j0 + tx] : 0.f;
                float bvB = (ks == 0) ? fbb[j0 + 64 + tx] : 0.f;
#pragma unroll
                for (int p = 0; p < 4; p++) {
                    int bA = ty * 8 + 2 * p;
                    float lo, hi;
                    unpack2(aA[p], lo, hi);
                    g_gatep[ks][bA * NE + j0 + tx] = lo + bvA;
                    g_gatep[ks][(bA + 1) * NE + j0 + tx] = hi + bvA;
                    unpack2(aB[p], lo, hi);
                    g_gatep[ks][bA * NE + j0 + 64 + tx] = lo + bvB;
                    g_gatep[ks][(bA + 1) * NE + j0 + 64 + tx] = hi + bvB;
                }
            }
        } else if (fcact) {
            // fc first half (K chunks 0-7); h = h after step t-1
            run_kmajor<8>(h, ND, fcW + fj0, NV, fvw, 0, fwact, fA, fB, Xs, Ws, tid);
        }
        gridbar(gen);

        // ---------------- W2 ----------------
        if (fcact) {
            run_kmajor<8>(h, ND, fcW + fj0, NV, fvw, 256, fwact, fA, fB, Xs, Ws, tid);
            int tprev = t - 1;
#pragma unroll
            for (int p = 0; p < 4; p++) {
                int bA = ty * 8 + 2 * p, bB = bA + 1;
                bool actA = tprev < sD[bA];
                bool actB = tprev < sD[bB];
                int cA = fj0 + tx, cB = fj0 + 64 + tx;
                float lo, hi;
                if (cA < NV) {
                    float bv = fcb[cA];
                    unpack2(fA[p], lo, hi);
                    out[OUT_PRED + (size_t)(bA * NT + tprev) * NV + cA] = actA ? lo + bv : 0.f;
                    out[OUT_PRED + (size_t)(bB * NT + tprev) * NV + cA] = actB ? hi + bv : 0.f;
                }
                if (cB < NV) {
                    float bv = fcb[cB];
                    unpack2(fB[p], lo, hi);
                    out[OUT_PRED + (size_t)(bA * NT + tprev) * NV + cB] = actA ? lo + bv : 0.f;
                    out[OUT_PRED + (size_t)(bB * NT + tprev) * NV + cB] = actB ? hi + bv : 0.f;
                }
            }
        } else if (t < NT) {
            int ab = (bid < 40) ? bid : ((bid >= 119 && bid < 143) ? bid - 79 : -1);
            if (ab >= 0) alpha_awe(ab, t, fullw, fullb, enc, out, sD, sO);
        }
        if (t == NT) break;
        gridbar(gen);

        // ---------------- W3: merged [h;awe] gates ----------------
        if (bid < 128) {
            int jt = bid & 15, ks = bid >> 4;
            int j0 = jt * 128;
            ull aA[4] = {}, aB[4] = {};
            run_mix<10>(h, g_awe, Whh + (size_t)j0 * ND, Wih + (size_t)j0 * NX,
                        ks * 320, wact, aA, aB, Xs, Ws, tid);
            if (wact) {
#pragma unroll
                for (int p = 0; p < 4; p++) {
                    int bA = ty * 8 + 2 * p;
                    float lo, hi;
                    unpack2(aA[p], lo, hi);
                    g_gawe[ks][bA * (4 * ND) + j0 + tx] = lo;
                    g_gawe[ks][(bA + 1) * (4 * ND) + j0 + tx] = hi;
                    unpack2(aB[p], lo, hi);
                    g_gawe[ks][bA * (4 * ND) + j0 + 64 + tx] = lo;
                    g_gawe[ks][(bA + 1) * (4 * ND) + j0 + 64 + tx] = hi;
                }
            }
        }
        gridbar(gen);

        // ---------------- W4: lstm ----------------
        if (bid < NB && t < sD[bid]) {
            const int b = bid, d = tid;
            float gv[4];
#pragma unroll
            for (int q = 0; q < 4; q++) {
                int j = q * ND + d;
                float s = g_embg[t][b * (4 * ND) + j];
#pragma unroll
                for (int ks = 0; ks < 8; ks++) s += g_gawe[ks][b * (4 * ND) + j];
                gv[q] = s;
            }
            float i_ = sigf(gv[0]);
            float f_ = sigf(gv[1]);
            float gg = tanhf(gv[2]);
            float o_ = sigf(gv[3]);
            float c = f_ * g_c[b * ND + d] + i_ * gg;
            g_c[b * ND + d] = c;
            g_h[(t & 1) ^ 1][b * ND + d] = o_ * tanhf(c);
        }
        gridbar(gen);
    }
}

// ---------------------------------------------------------------
extern "C" void kernel_launch(void* const* d_in, const int* in_sizes, int n_in,
                              void* d_out, int out_size) {
    (void)in_sizes; (void)n_in; (void)out_size;
    const float* enc     = (const float*)d_in[0];
    const int*   caps    = (const int*)d_in[1];
    const int*   clen    = (const int*)d_in[2];
    const float* embW    = (const float*)d_in[3];
    const float* attEncW = (const float*)d_in[4];
    const float* attEncB = (const float*)d_in[5];
    const float* attDecW = (const float*)d_in[6];
    const float* attDecB = (const float*)d_in[7];
    const float* fullW   = (const float*)d_in[8];
    const float* fullB   = (const float*)d_in[9];
    const float* Wih     = (const float*)d_in[10];
    const float* Whh     = (const float*)d_in[11];
    const float* bih     = (const float*)d_in[12];
    const float* bhh     = (const float*)d_in[13];
    const float* iHW     = (const float*)d_in[14];
    const float* iHb     = (const float*)d_in[15];
    const float* iCW     = (const float*)d_in[16];
    const float* iCb     = (const float*)d_in[17];
    const float* fbW     = (const float*)d_in[18];
    const float* fbb     = (const float*)d_in[19];
    const float* fcW     = (const float*)d_in[20];
    const float* fcb     = (const float*)d_in[21];
    float* out = (float*)d_out;

    const int SM_G128 = (2 * XS_ST + 2 * WS_ST) * 4;   // 51200
    const int SM_ATT1 = (4 * AXS_ST) * 4;              // 67584
    static int configured = 0;
    if (!configured) {
        cudaFuncSetAttribute(k_init, cudaFuncAttributeMaxDynamicSharedMemorySize, SM_G128);
        cudaFuncSetAttribute(k_embg, cudaFuncAttributeMaxDynamicSharedMemorySize, SM_G128);
        cudaFuncSetAttribute(k_att1, cudaFuncAttributeMaxDynamicSharedMemorySize, SM_ATT1);
        cudaFuncSetAttribute(k_loop, cudaFuncAttributeMaxDynamicSharedMemorySize, SM_G128);
        configured = 1;
    }

    k_sort<<<1, 64>>>(clen, caps, out);
    k_prep<<<512 + NT * NB, 256>>>(caps, embW, enc);
    k_init<<<32, 256, SM_G128>>>(iHW, iCW, iHb, iCb);
    k_embg<<<NT * 16, 256, SM_G128>>>(Wih, bih, bhh);
    k_att1<<<dim3(4, 98), 256, SM_ATT1>>>(enc, attEncW, attEncB);
    k_loop<<<NBLK, 512, SM_G128>>>(enc, attDecW, attDecB, fbW, fbb,
                                   fullW, fullB, Wih, Whh, fcW, fcb, out);
}